// round 1
// baseline (speedup 1.0000x reference)
#include <cuda_runtime.h>
#include <cuda_bf16.h>

// Problem constants
#define B_SZ   4
#define S_LEN  2048
#define D_MOD  1024
#define F_DIM  4096
#define N_HEAD 16
#define HD     64
#define ROWS   (B_SZ * S_LEN)        // 8192
#define LN_EPS 1e-5f

// ---------------- scratch (device globals; no allocation) ----------------
__device__ float g_h  [ROWS * D_MOD];   // LN1(x)
__device__ float g_q  [ROWS * D_MOD];
__device__ float g_k  [ROWS * D_MOD];
__device__ float g_v  [ROWS * D_MOD];
__device__ float g_ctx[ROWS * D_MOD];
__device__ float g_x1 [ROWS * D_MOD];   // x + ctx@Wo
__device__ float g_h2 [ROWS * D_MOD];   // LN2(x1)
__device__ float g_mid[ROWS * F_DIM];   // relu(h2@W1+b1)
__device__ float g_pool[B_SZ * D_MOD];

// ---------------- block reduction helper ----------------
__device__ __forceinline__ float block_sum_256(float v, float* sred) {
    int lane = threadIdx.x & 31, w = threadIdx.x >> 5;
    #pragma unroll
    for (int o = 16; o; o >>= 1) v += __shfl_xor_sync(0xffffffffu, v, o);
    if (lane == 0) sred[w] = v;
    __syncthreads();
    float r = (threadIdx.x < 8) ? sred[threadIdx.x] : 0.0f;
    if (w == 0) {
        #pragma unroll
        for (int o = 4; o; o >>= 1) r += __shfl_xor_sync(0x000000ffu, r, o);
        if (lane == 0) sred[0] = r;
    }
    __syncthreads();
    float out = sred[0];
    __syncthreads();
    return out;
}

// ---------------- LayerNorm: one block per row (D=1024, 256 thr) ----------------
__global__ void ln_kernel(const float* __restrict__ x, const float* __restrict__ w,
                          const float* __restrict__ b, float* __restrict__ out) {
    __shared__ float sred[8];
    size_t row = blockIdx.x;
    const float* xr = x + row * D_MOD;
    float v[4];
    int t = threadIdx.x;
    #pragma unroll
    for (int j = 0; j < 4; ++j) v[j] = xr[t + 256 * j];
    float s = v[0] + v[1] + v[2] + v[3];
    float mu = block_sum_256(s, sred) * (1.0f / D_MOD);
    float d2 = 0.f;
    #pragma unroll
    for (int j = 0; j < 4; ++j) { float d = v[j] - mu; d2 += d * d; }
    float var = block_sum_256(d2, sred) * (1.0f / D_MOD);
    float inv = rsqrtf(var + LN_EPS);
    float* orow = out + row * D_MOD;
    #pragma unroll
    for (int j = 0; j < 4; ++j) {
        int idx = t + 256 * j;
        orow[idx] = (v[j] - mu) * inv * w[idx] + b[idx];
    }
}

// ---------------- GEMM: C[M,N] = act(A[M,K] @ B[K,N] + bias + resid) ----------------
// 64x64 tile, BK=16, 256 threads, 4x4 microtile per thread.
#define BM 64
#define BN 64
#define BK 16

template <bool RELU>
__global__ void gemm_kernel(const float* __restrict__ A, const float* __restrict__ Bm,
                            const float* __restrict__ bias, const float* __restrict__ resid,
                            float* __restrict__ C, int M, int N, int K) {
    __shared__ float As[BK][BM + 4];
    __shared__ float Bs[BK][BN + 4];
    int t  = threadIdx.x;
    int tx = t & 15, ty = t >> 4;
    int m0 = blockIdx.y * BM, n0 = blockIdx.x * BN;

    int mA = t >> 2, kA = (t & 3) << 2;     // A tile load: row mA, 4 consecutive k
    int kB = t >> 4, nB = (t & 15) << 2;    // B tile load: row kB, 4 consecutive n

    const float* Aptr = A  + (size_t)(m0 + mA) * K + kA;
    const float* Bptr = Bm + (size_t)kB * N + n0 + nB;

    float c[4][4] = {};
    for (int k0 = 0; k0 < K; k0 += BK) {
        float4 av = *(const float4*)(Aptr + k0);
        float4 bv = *(const float4*)(Bptr + (size_t)k0 * N);
        As[kA + 0][mA] = av.x; As[kA + 1][mA] = av.y;
        As[kA + 2][mA] = av.z; As[kA + 3][mA] = av.w;
        *(float4*)&Bs[kB][nB] = bv;
        __syncthreads();
        #pragma unroll
        for (int kk = 0; kk < BK; ++kk) {
            float4 a = *(const float4*)&As[kk][ty << 2];
            float4 b = *(const float4*)&Bs[kk][tx << 2];
            c[0][0] += a.x * b.x; c[0][1] += a.x * b.y; c[0][2] += a.x * b.z; c[0][3] += a.x * b.w;
            c[1][0] += a.y * b.x; c[1][1] += a.y * b.y; c[1][2] += a.y * b.z; c[1][3] += a.y * b.w;
            c[2][0] += a.z * b.x; c[2][1] += a.z * b.y; c[2][2] += a.z * b.z; c[2][3] += a.z * b.w;
            c[3][0] += a.w * b.x; c[3][1] += a.w * b.y; c[3][2] += a.w * b.z; c[3][3] += a.w * b.w;
        }
        __syncthreads();
    }
    #pragma unroll
    for (int i = 0; i < 4; ++i) {
        int row = m0 + (ty << 2) + i;
        #pragma unroll
        for (int j = 0; j < 4; ++j) {
            int col = n0 + (tx << 2) + j;
            float v = c[i][j];
            if (bias)  v += bias[col];
            if (resid) v += resid[(size_t)row * N + col];
            if (RELU)  v = fmaxf(v, 0.0f);
            C[(size_t)row * N + col] = v;
        }
    }
}

// ---------------- Flash attention (causal), 64-query blocks ----------------
// grid = (S/64, B*H); block = 256 (8 warps x 8 queries; lane owns keys/dims {l, l+32})
#define BQ 64

__global__ __launch_bounds__(256) void attn_kernel(const float* __restrict__ q,
                                                   const float* __restrict__ k,
                                                   const float* __restrict__ v,
                                                   float* __restrict__ ctx) {
    __shared__ float Qs[BQ][HD];
    __shared__ float KP[BQ][HD];   // holds swizzled K, then P
    __shared__ float Vs[BQ][HD];

    int qb = blockIdx.x;
    int bh = blockIdx.y;
    int b  = bh / N_HEAD, h = bh % N_HEAD;
    size_t base = (size_t)b * S_LEN * D_MOD + (size_t)h * HD;
    const float* qp = q + base;
    const float* kp = k + base;
    const float* vp = v + base;

    int tid  = threadIdx.x;
    int warp = tid >> 5, lane = tid & 31;
    int q8 = warp * 8;
    int k0i = lane, k1i = lane + 32;

    for (int i = tid; i < BQ * HD; i += 256) {
        int r = i >> 6, c = i & 63;
        Qs[r][c] = qp[(size_t)(qb * BQ + r) * D_MOD + c];
    }

    float m[8], lsum[8], acc0[8], acc1[8];
    #pragma unroll
    for (int i = 0; i < 8; ++i) { m[i] = -1e30f; lsum[i] = 0.f; acc0[i] = 0.f; acc1[i] = 0.f; }

    const float scale = 0.125f; // 1/sqrt(64)
    int ntiles = qb + 1;
    for (int tile = 0; tile < ntiles; ++tile) {
        __syncthreads();
        for (int i = tid; i < BQ * HD; i += 256) {
            int r = i >> 6, c = i & 63;
            KP[r][(c + r) & 63] = kp[(size_t)(tile * BQ + r) * D_MOD + c];  // swizzled K
            Vs[r][c]            = vp[(size_t)(tile * BQ + r) * D_MOD + c];
        }
        __syncthreads();

        float s0[8] = {}, s1[8] = {};
        #pragma unroll 4
        for (int d = 0; d < HD; ++d) {
            float kv0 = KP[k0i][(d + k0i) & 63];
            float kv1 = KP[k1i][(d + k1i) & 63];
            #pragma unroll
            for (int qi = 0; qi < 8; ++qi) {
                float qv = Qs[q8 + qi][d];
                s0[qi] += qv * kv0;
                s1[qi] += qv * kv1;
            }
        }

        bool diag = (tile == qb);
        #pragma unroll
        for (int qi = 0; qi < 8; ++qi) {
            float a0 = s0[qi] * scale, a1 = s1[qi] * scale;
            if (diag) {
                int qg = q8 + qi;
                if (k0i > qg) a0 = -1e30f;
                if (k1i > qg) a1 = -1e30f;
            }
            float mx = fmaxf(a0, a1);
            #pragma unroll
            for (int o = 16; o; o >>= 1) mx = fmaxf(mx, __shfl_xor_sync(0xffffffffu, mx, o));
            float mnew = fmaxf(m[qi], mx);
            float corr = __expf(m[qi] - mnew);
            float p0 = __expf(a0 - mnew);
            float p1 = __expf(a1 - mnew);
            float ps = p0 + p1;
            #pragma unroll
            for (int o = 16; o; o >>= 1) ps += __shfl_xor_sync(0xffffffffu, ps, o);
            lsum[qi] = lsum[qi] * corr + ps;
            acc0[qi] *= corr;
            acc1[qi] *= corr;
            m[qi] = mnew;
            s0[qi] = p0; s1[qi] = p1;
        }

        __syncthreads();                 // everyone done reading K before P overwrites
        #pragma unroll
        for (int qi = 0; qi < 8; ++qi) {
            KP[q8 + qi][k0i] = s0[qi];
            KP[q8 + qi][k1i] = s1[qi];
        }
        __syncwarp();

        #pragma unroll 4
        for (int kk = 0; kk < BQ; ++kk) {
            float v0 = Vs[kk][k0i];
            float v1 = Vs[kk][k1i];
            #pragma unroll
            for (int qi = 0; qi < 8; ++qi) {
                float p = KP[q8 + qi][kk];
                acc0[qi] += p * v0;
                acc1[qi] += p * v1;
            }
        }
    }

    #pragma unroll
    for (int qi = 0; qi < 8; ++qi) {
        float inv = 1.0f / lsum[qi];
        size_t row = ((size_t)b * S_LEN + qb * BQ + q8 + qi) * D_MOD + (size_t)h * HD;
        ctx[row + k0i] = acc0[qi] * inv;
        ctx[row + k1i] = acc1[qi] * inv;
    }
}

// ---------------- confidence head ----------------
__global__ void pool_kernel(const float* __restrict__ xo, float* __restrict__ pooled) {
    int idx = blockIdx.x * blockDim.x + threadIdx.x; // 4096 = B*D
    int b = idx >> 10, d = idx & 1023;
    const float* p = xo + (size_t)b * S_LEN * D_MOD + d;
    float s = 0.f;
    #pragma unroll 8
    for (int t = 0; t < S_LEN; ++t) s += p[(size_t)t * D_MOD];
    pooled[idx] = s * (1.0f / S_LEN);
}

__global__ void conf_kernel(const float* __restrict__ pooled, const float* __restrict__ cw,
                            const float* __restrict__ cb, float* __restrict__ out) {
    __shared__ float sred[8];
    float acc[B_SZ] = {};
    for (int d = threadIdx.x; d < D_MOD; d += 256) {
        float w = cw[d];
        #pragma unroll
        for (int b = 0; b < B_SZ; ++b) acc[b] += pooled[b * D_MOD + d] * w;
    }
    float dots[B_SZ];
    #pragma unroll
    for (int b = 0; b < B_SZ; ++b) dots[b] = block_sum_256(acc[b], sred);
    if (threadIdx.x == 0) {
        float s = 0.f;
        #pragma unroll
        for (int b = 0; b < B_SZ; ++b) s += 1.0f / (1.0f + __expf(-(dots[b] + cb[0])));
        out[0] = s * (1.0f / B_SZ);
    }
}

// ---------------- host launch ----------------
static float* sym(const void* s) {
    void* p = nullptr;
    cudaGetSymbolAddress(&p, s);
    return (float*)p;
}

extern "C" void kernel_launch(void* const* d_in, const int* in_sizes, int n_in,
                              void* d_out, int out_size) {
    const float* x      = (const float*)d_in[0];
    const float* Wq     = (const float*)d_in[1];
    const float* Wk     = (const float*)d_in[2];
    const float* Wv     = (const float*)d_in[3];
    const float* Wo     = (const float*)d_in[4];
    const float* ln1_w  = (const float*)d_in[5];
    const float* ln1_b  = (const float*)d_in[6];
    const float* W1     = (const float*)d_in[7];
    const float* b1     = (const float*)d_in[8];
    const float* W2     = (const float*)d_in[9];
    const float* b2     = (const float*)d_in[10];
    const float* ln2_w  = (const float*)d_in[11];
    const float* ln2_b  = (const float*)d_in[12];
    const float* conf_w = (const float*)d_in[13];
    const float* conf_b = (const float*)d_in[14];
    float* out = (float*)d_out;

    float* h   = sym(g_h);
    float* q   = sym(g_q);
    float* k   = sym(g_k);
    float* v   = sym(g_v);
    float* ctx = sym(g_ctx);
    float* x1  = sym(g_x1);
    float* h2  = sym(g_h2);
    float* mid = sym(g_mid);
    float* pl  = sym(g_pool);

    dim3 gD(D_MOD / BN, ROWS / BM);   // (16, 128)
    dim3 gF(F_DIM / BN, ROWS / BM);   // (64, 128)

    // LN1
    ln_kernel<<<ROWS, 256>>>(x, ln1_w, ln1_b, h);
    // QKV projections
    gemm_kernel<false><<<gD, 256>>>(h, Wq, nullptr, nullptr, q, ROWS, D_MOD, D_MOD);
    gemm_kernel<false><<<gD, 256>>>(h, Wk, nullptr, nullptr, k, ROWS, D_MOD, D_MOD);
    gemm_kernel<false><<<gD, 256>>>(h, Wv, nullptr, nullptr, v, ROWS, D_MOD, D_MOD);
    // causal attention
    dim3 gA(S_LEN / BQ, B_SZ * N_HEAD);   // (32, 64)
    attn_kernel<<<gA, 256>>>(q, k, v, ctx);
    // out-proj + residual
    gemm_kernel<false><<<gD, 256>>>(ctx, Wo, nullptr, x, x1, ROWS, D_MOD, D_MOD);
    // LN2
    ln_kernel<<<ROWS, 256>>>(x1, ln2_w, ln2_b, h2);
    // FFN
    gemm_kernel<true ><<<gF, 256>>>(h2, W1, b1, nullptr, mid, ROWS, F_DIM, D_MOD);
    gemm_kernel<false><<<gD, 256>>>(mid, W2, b2, x1, out, ROWS, D_MOD, F_DIM);
    // confidence head
    pool_kernel<<<16, 256>>>(out, pl);
    conf_kernel<<<1, 256>>>(pl, conf_w, conf_b, out + (out_size - 1));
}

// round 3
// speedup vs baseline: 1.9800x; 1.9800x over previous
#include <cuda_runtime.h>
#include <cuda_bf16.h>
#include <cstdint>

// Problem constants
#define B_SZ   4
#define S_LEN  2048
#define D_MOD  1024
#define F_DIM  4096
#define N_HEAD 16
#define HD     64
#define ROWS   (B_SZ * S_LEN)        // 8192
#define LN_EPS 1e-5f

// ---------------- scratch (device globals; no allocation) ----------------
__device__ float g_h  [ROWS * D_MOD];   // LN1(x)
__device__ float g_q  [ROWS * D_MOD];
__device__ float g_k  [ROWS * D_MOD];
__device__ float g_v  [ROWS * D_MOD];
__device__ float g_ctx[ROWS * D_MOD];
__device__ float g_x1 [ROWS * D_MOD];   // x + ctx@Wo
__device__ float g_h2 [ROWS * D_MOD];   // LN2(x1)
__device__ float g_mid[ROWS * F_DIM];   // relu(h2@W1+b1)
__device__ float g_pool[B_SZ * D_MOD];

// ======================= HMMA (mma.sync) helpers =======================
__device__ __forceinline__ uint32_t smem_u32(const void* p) {
    uint32_t a;
    asm("{ .reg .u64 t; cvta.to.shared.u64 t, %1; cvt.u32.u64 %0, t; }" : "=r"(a) : "l"(p));
    return a;
}

__device__ __forceinline__ void ldm_x4(uint32_t* r, uint32_t addr) {
    asm volatile("ldmatrix.sync.aligned.m8n8.x4.shared.b16 {%0,%1,%2,%3}, [%4];"
        : "=r"(r[0]), "=r"(r[1]), "=r"(r[2]), "=r"(r[3]) : "r"(addr));
}

__device__ __forceinline__ void ldm_x2t(uint32_t* r, uint32_t addr) {
    asm volatile("ldmatrix.sync.aligned.m8n8.x2.trans.shared.b16 {%0,%1}, [%2];"
        : "=r"(r[0]), "=r"(r[1]) : "r"(addr));
}

__device__ __forceinline__ void mma_bf16(float* c, const uint32_t* a, const uint32_t* b) {
    asm volatile(
        "mma.sync.aligned.m16n8k16.row.col.f32.bf16.bf16.f32 "
        "{%0,%1,%2,%3}, {%4,%5,%6,%7}, {%8,%9}, {%0,%1,%2,%3};"
        : "+f"(c[0]), "+f"(c[1]), "+f"(c[2]), "+f"(c[3])
        : "r"(a[0]), "r"(a[1]), "r"(a[2]), "r"(a[3]), "r"(b[0]), "r"(b[1]));
}

__device__ __forceinline__ uint32_t pack_bf16x2(__nv_bfloat16 a, __nv_bfloat16 b) {
    __nv_bfloat162 v; v.x = a; v.y = b;
    return *reinterpret_cast<uint32_t*>(&v);
}

// ======================= tensor-core GEMM (mma.sync bf16, 3-term split) =======================
// C[M,N] = act(A[M,K] @ B[K,N] + bias + resid), fp32 in/out.
// CTA tile 128x128, BK=32, 256 threads; warp grid 2(m) x 4(n); warp tile 64x32.
// SMEM: A rows padded to 80B, B rows to 272B -> conflict-free ldmatrix.

#define TCBM 128
#define TCBN 128
#define TCBK 32
#define A_PITCH 80     // bytes per A smem row (32 bf16 data + pad)
#define B_PITCH 272    // bytes per B smem row (128 bf16 data + pad)

#define SM_A_HI 0
#define SM_A_LO (SM_A_HI + 128 * A_PITCH)        // 10240
#define SM_B_HI (SM_A_LO + 128 * A_PITCH)        // 20480
#define SM_B_LO (SM_B_HI + 32 * B_PITCH)         // 29184
#define SM_TOT  (SM_B_LO + 32 * B_PITCH)         // 37888

template <bool RELU>
__global__ __launch_bounds__(256, 2) void hmma_gemm(
    const float* __restrict__ A, const float* __restrict__ Bm,
    const float* __restrict__ bias, const float* __restrict__ resid,
    float* __restrict__ C, int M, int N, int K)
{
    __shared__ char smem[SM_TOT];
    const uint32_t sb = smem_u32(smem);

    const int tid = threadIdx.x;
    const int wid = tid >> 5, lane = tid & 31;
    const int warp_m = wid & 1;        // 0..1 -> 64 rows each
    const int warp_n = wid >> 1;       // 0..3 -> 32 cols each
    const int m0 = blockIdx.y * TCBM, n0 = blockIdx.x * TCBN;

    float c[4][4][4];                  // [mt][nt][frag]
    #pragma unroll
    for (int i = 0; i < 4; ++i)
        #pragma unroll
        for (int j = 0; j < 4; ++j)
            #pragma unroll
            for (int f = 0; f < 4; ++f) c[i][j][f] = 0.f;

    // ldmatrix lane-address components (hoisted)
    const uint32_t a_row = (uint32_t)(warp_m * 64 + (lane & 15));     // + mt*16
    const uint32_t a_cb  = (uint32_t)((lane >> 4) << 4);              // + ks*32
    const uint32_t b_k   = (uint32_t)(lane & 15);                     // + ks*16
    const uint32_t b_cb  = (uint32_t)((warp_n * 32) * 2);             // + nt*16

    for (int k0 = 0; k0 < K; k0 += TCBK) {
        // ---- load + split-convert A tile (128 x 32 fp32) ----
        #pragma unroll
        for (int it = 0; it < 4; ++it) {
            int idx = it * 256 + tid;              // 0..1023
            int r = idx >> 3, cc = (idx & 7) << 2; // row, col (fp32 idx)
            float4 a = *(const float4*)(A + (size_t)(m0 + r) * K + k0 + cc);
            __nv_bfloat16 h0 = __float2bfloat16(a.x);
            __nv_bfloat16 h1 = __float2bfloat16(a.y);
            __nv_bfloat16 h2 = __float2bfloat16(a.z);
            __nv_bfloat16 h3 = __float2bfloat16(a.w);
            __nv_bfloat16 l0 = __float2bfloat16(a.x - __bfloat162float(h0));
            __nv_bfloat16 l1 = __float2bfloat16(a.y - __bfloat162float(h1));
            __nv_bfloat16 l2 = __float2bfloat16(a.z - __bfloat162float(h2));
            __nv_bfloat16 l3 = __float2bfloat16(a.w - __bfloat162float(h3));
            int off = r * A_PITCH + cc * 2;
            *(uint2*)(smem + SM_A_HI + off) = make_uint2(pack_bf16x2(h0, h1), pack_bf16x2(h2, h3));
            *(uint2*)(smem + SM_A_LO + off) = make_uint2(pack_bf16x2(l0, l1), pack_bf16x2(l2, l3));
        }
        // ---- load + split-convert B tile (32 x 128 fp32) ----
        #pragma unroll
        for (int it = 0; it < 4; ++it) {
            int idx = it * 256 + tid;
            int r = idx >> 5, cc = (idx & 31) << 2;
            float4 b = *(const float4*)(Bm + (size_t)(k0 + r) * N + n0 + cc);
            __nv_bfloat16 h0 = __float2bfloat16(b.x);
            __nv_bfloat16 h1 = __float2bfloat16(b.y);
            __nv_bfloat16 h2 = __float2bfloat16(b.z);
            __nv_bfloat16 h3 = __float2bfloat16(b.w);
            __nv_bfloat16 l0 = __float2bfloat16(b.x - __bfloat162float(h0));
            __nv_bfloat16 l1 = __float2bfloat16(b.y - __bfloat162float(h1));
            __nv_bfloat16 l2 = __float2bfloat16(b.z - __bfloat162float(h2));
            __nv_bfloat16 l3 = __float2bfloat16(b.w - __bfloat162float(h3));
            int off = r * B_PITCH + cc * 2;
            *(uint2*)(smem + SM_B_HI + off) = make_uint2(pack_bf16x2(h0, h1), pack_bf16x2(h2, h3));
            *(uint2*)(smem + SM_B_LO + off) = make_uint2(pack_bf16x2(l0, l1), pack_bf16x2(l2, l3));
        }
        __syncthreads();

        // ---- 2 k-steps of m16n8k16 ----
        #pragma unroll
        for (int ks = 0; ks < 2; ++ks) {
            uint32_t bh[4][2], bl[4][2];
            uint32_t b_addr = sb + (b_k + ks * 16) * B_PITCH + b_cb;
            #pragma unroll
            for (int nt = 0; nt < 4; ++nt) {
                ldm_x2t(bh[nt], b_addr + SM_B_HI + nt * 16);
                ldm_x2t(bl[nt], b_addr + SM_B_LO + nt * 16);
            }
            uint32_t a_addr = sb + a_row * A_PITCH + a_cb + ks * 32;
            #pragma unroll
            for (int mt = 0; mt < 4; ++mt) {
                uint32_t ah[4], al[4];
                ldm_x4(ah, a_addr + SM_A_HI + mt * 16 * A_PITCH);
                ldm_x4(al, a_addr + SM_A_LO + mt * 16 * A_PITCH);
                #pragma unroll
                for (int nt = 0; nt < 4; ++nt) {
                    mma_bf16(c[mt][nt], ah, bh[nt]);
                    mma_bf16(c[mt][nt], ah, bl[nt]);
                    mma_bf16(c[mt][nt], al, bh[nt]);
                }
            }
        }
        __syncthreads();
    }

    // ---- epilogue ----
    const int er = lane >> 2, ec = (lane & 3) * 2;
    #pragma unroll
    for (int mt = 0; mt < 4; ++mt) {
        #pragma unroll
        for (int nt = 0; nt < 4; ++nt) {
            int gr = m0 + warp_m * 64 + mt * 16 + er;
            int gc = n0 + warp_n * 32 + nt * 8 + ec;
            #pragma unroll
            for (int half = 0; half < 2; ++half) {
                int row = gr + half * 8;
                float v0 = c[mt][nt][half * 2 + 0];
                float v1 = c[mt][nt][half * 2 + 1];
                if (bias) { v0 += bias[gc]; v1 += bias[gc + 1]; }
                if (resid) {
                    float2 r2 = *(const float2*)(resid + (size_t)row * N + gc);
                    v0 += r2.x; v1 += r2.y;
                }
                if (RELU) { v0 = fmaxf(v0, 0.f); v1 = fmaxf(v1, 0.f); }
                *(float2*)(C + (size_t)row * N + gc) = make_float2(v0, v1);
            }
        }
    }
}

// ---------------- block reduction helper ----------------
__device__ __forceinline__ float block_sum_256(float v, float* sred) {
    int lane = threadIdx.x & 31, w = threadIdx.x >> 5;
    #pragma unroll
    for (int o = 16; o; o >>= 1) v += __shfl_xor_sync(0xffffffffu, v, o);
    if (lane == 0) sred[w] = v;
    __syncthreads();
    float r = (threadIdx.x < 8) ? sred[threadIdx.x] : 0.0f;
    if (w == 0) {
        #pragma unroll
        for (int o = 4; o; o >>= 1) r += __shfl_xor_sync(0x000000ffu, r, o);
        if (lane == 0) sred[0] = r;
    }
    __syncthreads();
    float out = sred[0];
    __syncthreads();
    return out;
}

// ---------------- LayerNorm: one block per row (D=1024, 256 thr) ----------------
__global__ void ln_kernel(const float* __restrict__ x, const float* __restrict__ w,
                          const float* __restrict__ b, float* __restrict__ out) {
    __shared__ float sred[8];
    size_t row = blockIdx.x;
    const float* xr = x + row * D_MOD;
    float v[4];
    int t = threadIdx.x;
    #pragma unroll
    for (int j = 0; j < 4; ++j) v[j] = xr[t + 256 * j];
    float s = v[0] + v[1] + v[2] + v[3];
    float mu = block_sum_256(s, sred) * (1.0f / D_MOD);
    float d2 = 0.f;
    #pragma unroll
    for (int j = 0; j < 4; ++j) { float d = v[j] - mu; d2 += d * d; }
    float var = block_sum_256(d2, sred) * (1.0f / D_MOD);
    float inv = rsqrtf(var + LN_EPS);
    float* orow = out + row * D_MOD;
    #pragma unroll
    for (int j = 0; j < 4; ++j) {
        int idx = t + 256 * j;
        orow[idx] = (v[j] - mu) * inv * w[idx] + b[idx];
    }
}

// ---------------- Flash attention (causal), 64-query blocks ----------------
#define BQ 64

__global__ __launch_bounds__(256) void attn_kernel(const float* __restrict__ q,
                                                   const float* __restrict__ k,
                                                   const float* __restrict__ v,
                                                   float* __restrict__ ctx) {
    __shared__ float Qs[BQ][HD];
    __shared__ float KP[BQ][HD];   // holds swizzled K, then P
    __shared__ float Vs[BQ][HD];

    int qb = blockIdx.x;
    int bh = blockIdx.y;
    int b  = bh / N_HEAD, h = bh % N_HEAD;
    size_t base = (size_t)b * S_LEN * D_MOD + (size_t)h * HD;
    const float* qp = q + base;
    const float* kp = k + base;
    const float* vp = v + base;

    int tid  = threadIdx.x;
    int warp = tid >> 5, lane = tid & 31;
    int q8 = warp * 8;
    int k0i = lane, k1i = lane + 32;

    for (int i = tid; i < BQ * HD; i += 256) {
        int r = i >> 6, c = i & 63;
        Qs[r][c] = qp[(size_t)(qb * BQ + r) * D_MOD + c];
    }

    float m[8], lsum[8], acc0[8], acc1[8];
    #pragma unroll
    for (int i = 0; i < 8; ++i) { m[i] = -1e30f; lsum[i] = 0.f; acc0[i] = 0.f; acc1[i] = 0.f; }

    const float scale = 0.125f; // 1/sqrt(64)
    int ntiles = qb + 1;
    for (int tile = 0; tile < ntiles; ++tile) {
        __syncthreads();
        for (int i = tid; i < BQ * HD; i += 256) {
            int r = i >> 6, c = i & 63;
            KP[r][(c + r) & 63] = kp[(size_t)(tile * BQ + r) * D_MOD + c];  // swizzled K
            Vs[r][c]            = vp[(size_t)(tile * BQ + r) * D_MOD + c];
        }
        __syncthreads();

        float s0[8] = {}, s1[8] = {};
        #pragma unroll 4
        for (int d = 0; d < HD; ++d) {
            float kv0 = KP[k0i][(d + k0i) & 63];
            float kv1 = KP[k1i][(d + k1i) & 63];
            #pragma unroll
            for (int qi = 0; qi < 8; ++qi) {
                float qv = Qs[q8 + qi][d];
                s0[qi] += qv * kv0;
                s1[qi] += qv * kv1;
            }
        }

        bool diag = (tile == qb);
        #pragma unroll
        for (int qi = 0; qi < 8; ++qi) {
            float a0 = s0[qi] * scale, a1 = s1[qi] * scale;
            if (diag) {
                int qg = q8 + qi;
                if (k0i > qg) a0 = -1e30f;
                if (k1i > qg) a1 = -1e30f;
            }
            float mx = fmaxf(a0, a1);
            #pragma unroll
            for (int o = 16; o; o >>= 1) mx = fmaxf(mx, __shfl_xor_sync(0xffffffffu, mx, o));
            float mnew = fmaxf(m[qi], mx);
            float corr = __expf(m[qi] - mnew);
            float p0 = __expf(a0 - mnew);
            float p1 = __expf(a1 - mnew);
            float ps = p0 + p1;
            #pragma unroll
            for (int o = 16; o; o >>= 1) ps += __shfl_xor_sync(0xffffffffu, ps, o);
            lsum[qi] = lsum[qi] * corr + ps;
            acc0[qi] *= corr;
            acc1[qi] *= corr;
            m[qi] = mnew;
            s0[qi] = p0; s1[qi] = p1;
        }

        __syncthreads();                 // everyone done reading K before P overwrites
        #pragma unroll
        for (int qi = 0; qi < 8; ++qi) {
            KP[q8 + qi][k0i] = s0[qi];
            KP[q8 + qi][k1i] = s1[qi];
        }
        __syncwarp();

        #pragma unroll 4
        for (int kk = 0; kk < BQ; ++kk) {
            float v0 = Vs[kk][k0i];
            float v1 = Vs[kk][k1i];
            #pragma unroll
            for (int qi = 0; qi < 8; ++qi) {
                float p = KP[q8 + qi][kk];
                acc0[qi] += p * v0;
                acc1[qi] += p * v1;
            }
        }
    }

    #pragma unroll
    for (int qi = 0; qi < 8; ++qi) {
        float inv = 1.0f / lsum[qi];
        size_t row = ((size_t)b * S_LEN + qb * BQ + q8 + qi) * D_MOD + (size_t)h * HD;
        ctx[row + k0i] = acc0[qi] * inv;
        ctx[row + k1i] = acc1[qi] * inv;
    }
}

// ---------------- confidence head ----------------
__global__ void pool_kernel(const float* __restrict__ xo, float* __restrict__ pooled) {
    int idx = blockIdx.x * blockDim.x + threadIdx.x; // 4096 = B*D
    int b = idx >> 10, d = idx & 1023;
    const float* p = xo + (size_t)b * S_LEN * D_MOD + d;
    float s = 0.f;
    #pragma unroll 8
    for (int t = 0; t < S_LEN; ++t) s += p[(size_t)t * D_MOD];
    pooled[idx] = s * (1.0f / S_LEN);
}

__global__ void conf_kernel(const float* __restrict__ pooled, const float* __restrict__ cw,
                            const float* __restrict__ cb, float* __restrict__ out) {
    __shared__ float sred[8];
    float acc[B_SZ] = {};
    for (int d = threadIdx.x; d < D_MOD; d += 256) {
        float w = cw[d];
        #pragma unroll
        for (int b = 0; b < B_SZ; ++b) acc[b] += pooled[b * D_MOD + d] * w;
    }
    float dots[B_SZ];
    #pragma unroll
    for (int b = 0; b < B_SZ; ++b) dots[b] = block_sum_256(acc[b], sred);
    if (threadIdx.x == 0) {
        float s = 0.f;
        #pragma unroll
        for (int b = 0; b < B_SZ; ++b) s += 1.0f / (1.0f + __expf(-(dots[b] + cb[0])));
        out[0] = s * (1.0f / B_SZ);
    }
}

// ---------------- host launch ----------------
static float* sym(const void* s) {
    void* p = nullptr;
    cudaGetSymbolAddress(&p, s);
    return (float*)p;
}

extern "C" void kernel_launch(void* const* d_in, const int* in_sizes, int n_in,
                              void* d_out, int out_size) {
    const float* x      = (const float*)d_in[0];
    const float* Wq     = (const float*)d_in[1];
    const float* Wk     = (const float*)d_in[2];
    const float* Wv     = (const float*)d_in[3];
    const float* Wo     = (const float*)d_in[4];
    const float* ln1_w  = (const float*)d_in[5];
    const float* ln1_b  = (const float*)d_in[6];
    const float* W1     = (const float*)d_in[7];
    const float* b1     = (const float*)d_in[8];
    const float* W2     = (const float*)d_in[9];
    const float* b2     = (const float*)d_in[10];
    const float* ln2_w  = (const float*)d_in[11];
    const float* ln2_b  = (const float*)d_in[12];
    const float* conf_w = (const float*)d_in[13];
    const float* conf_b = (const float*)d_in[14];
    float* out = (float*)d_out;

    float* h   = sym(g_h);
    float* q   = sym(g_q);
    float* k   = sym(g_k);
    float* v   = sym(g_v);
    float* ctx = sym(g_ctx);
    float* x1  = sym(g_x1);
    float* h2  = sym(g_h2);
    float* mid = sym(g_mid);
    float* pl  = sym(g_pool);

    dim3 gD(D_MOD / TCBN, ROWS / TCBM);   // (8, 64)
    dim3 gF(F_DIM / TCBN, ROWS / TCBM);   // (32, 64)

    // LN1
    ln_kernel<<<ROWS, 256>>>(x, ln1_w, ln1_b, h);
    // QKV projections (tensor cores, bf16 3-term split)
    hmma_gemm<false><<<gD, 256>>>(h, Wq, nullptr, nullptr, q, ROWS, D_MOD, D_MOD);
    hmma_gemm<false><<<gD, 256>>>(h, Wk, nullptr, nullptr, k, ROWS, D_MOD, D_MOD);
    hmma_gemm<false><<<gD, 256>>>(h, Wv, nullptr, nullptr, v, ROWS, D_MOD, D_MOD);
    // causal attention
    dim3 gA(S_LEN / BQ, B_SZ * N_HEAD);   // (32, 64)
    attn_kernel<<<gA, 256>>>(q, k, v, ctx);
    // out-proj + residual
    hmma_gemm<false><<<gD, 256>>>(ctx, Wo, nullptr, x, x1, ROWS, D_MOD, D_MOD);
    // LN2
    ln_kernel<<<ROWS, 256>>>(x1, ln2_w, ln2_b, h2);
    // FFN
    hmma_gemm<true ><<<gF, 256>>>(h2, W1, b1, nullptr, mid, ROWS, F_DIM, D_MOD);
    hmma_gemm<false><<<gD, 256>>>(mid, W2, b2, x1, out, ROWS, D_MOD, F_DIM);
    // confidence head
    pool_kernel<<<16, 256>>>(out, pl);
    conf_kernel<<<1, 256>>>(pl, conf_w, conf_b, out + (out_size - 1));
}

// round 4
// speedup vs baseline: 1.9914x; 1.0058x over previous
#include <cuda_runtime.h>
#include <cuda_bf16.h>
#include <cstdint>

// Problem constants
#define B_SZ   4
#define S_LEN  2048
#define D_MOD  1024
#define F_DIM  4096
#define N_HEAD 16
#define HD     64
#define ROWS   (B_SZ * S_LEN)        // 8192
#define QKV_N  (3 * D_MOD)           // 3072
#define LN_EPS 1e-5f

// ---------------- scratch (device globals; no allocation) ----------------
__device__ __nv_bfloat16 g_h_hi [ROWS * D_MOD];   // LN out (hi) -- reused for LN1 and LN2
__device__ __nv_bfloat16 g_h_lo [ROWS * D_MOD];
__device__ float         g_qkv  [ROWS * QKV_N];   // fused QKV output (fp32)
__device__ __nv_bfloat16 g_ctx_hi[ROWS * D_MOD];
__device__ __nv_bfloat16 g_ctx_lo[ROWS * D_MOD];
__device__ float         g_x1  [ROWS * D_MOD];    // x + ctx@Wo
__device__ __nv_bfloat16 g_mid_hi[ROWS * F_DIM];
__device__ __nv_bfloat16 g_mid_lo[ROWS * F_DIM];
__device__ float         g_pool[B_SZ * D_MOD];
// converted weights
__device__ __nv_bfloat16 g_wqkv_hi[D_MOD * QKV_N];
__device__ __nv_bfloat16 g_wqkv_lo[D_MOD * QKV_N];
__device__ __nv_bfloat16 g_wo_hi [D_MOD * D_MOD];
__device__ __nv_bfloat16 g_wo_lo [D_MOD * D_MOD];
__device__ __nv_bfloat16 g_w1_hi [D_MOD * F_DIM];
__device__ __nv_bfloat16 g_w1_lo [D_MOD * F_DIM];
__device__ __nv_bfloat16 g_w2_hi [F_DIM * D_MOD];
__device__ __nv_bfloat16 g_w2_lo [F_DIM * D_MOD];

// ======================= helpers =======================
__device__ __forceinline__ uint32_t smem_u32(const void* p) {
    uint32_t a;
    asm("{ .reg .u64 t; cvta.to.shared.u64 t, %1; cvt.u32.u64 %0, t; }" : "=r"(a) : "l"(p));
    return a;
}
__device__ __forceinline__ void ldm_x4(uint32_t* r, uint32_t addr) {
    asm volatile("ldmatrix.sync.aligned.m8n8.x4.shared.b16 {%0,%1,%2,%3}, [%4];"
        : "=r"(r[0]), "=r"(r[1]), "=r"(r[2]), "=r"(r[3]) : "r"(addr));
}
__device__ __forceinline__ void ldm_x4t(uint32_t* r, uint32_t addr) {
    asm volatile("ldmatrix.sync.aligned.m8n8.x4.trans.shared.b16 {%0,%1,%2,%3}, [%4];"
        : "=r"(r[0]), "=r"(r[1]), "=r"(r[2]), "=r"(r[3]) : "r"(addr));
}
__device__ __forceinline__ void mma_bf16(float* c, const uint32_t* a, const uint32_t* b) {
    asm volatile(
        "mma.sync.aligned.m16n8k16.row.col.f32.bf16.bf16.f32 "
        "{%0,%1,%2,%3}, {%4,%5,%6,%7}, {%8,%9}, {%0,%1,%2,%3};"
        : "+f"(c[0]), "+f"(c[1]), "+f"(c[2]), "+f"(c[3])
        : "r"(a[0]), "r"(a[1]), "r"(a[2]), "r"(a[3]), "r"(b[0]), "r"(b[1]));
}
__device__ __forceinline__ void cp16(uint32_t dst, const void* src) {
    asm volatile("cp.async.cg.shared.global [%0], [%1], 16;" :: "r"(dst), "l"(src));
}
__device__ __forceinline__ void cp_commit() {
    asm volatile("cp.async.commit_group;" ::: "memory");
}
__device__ __forceinline__ void cp_wait1() {
    asm volatile("cp.async.wait_group 1;" ::: "memory");
}
__device__ __forceinline__ void cp_wait0() {
    asm volatile("cp.async.wait_group 0;" ::: "memory");
}
__device__ __forceinline__ uint32_t pack_bf16x2(__nv_bfloat16 a, __nv_bfloat16 b) {
    __nv_bfloat162 v; v.x = a; v.y = b;
    return *reinterpret_cast<uint32_t*>(&v);
}
__device__ __forceinline__ void split1(float x, __nv_bfloat16& h, __nv_bfloat16& l) {
    h = __float2bfloat16(x);
    l = __float2bfloat16(x - __bfloat162float(h));
}

// ======================= pipelined HMMA GEMM =======================
// C[M,N] = act(A @ B + bias + resid); A,B given as pre-split bf16 hi/lo planes.
// CTA tile 128x128, BK=32, 256 threads, warp grid 2(m) x 4(n), warp tile 64x32.
// cp.async double-buffered; A rows padded to 80B, B rows to 272B (conflict-free ldmatrix).

#define TCBM 128
#define TCBN 128
#define TCBK 32
#define A_PITCH 80
#define B_PITCH 272
#define SM_A_HI 0
#define SM_A_LO 10240
#define SM_B_HI 20480
#define SM_B_LO 29184
#define SM_BUF  37888
#define SM_TOT  (2 * SM_BUF)    // 75776

template <bool RELU, bool SPLIT>
__global__ __launch_bounds__(256, 2) void hmma_gemm(
    const __nv_bfloat16* __restrict__ Ahi, const __nv_bfloat16* __restrict__ Alo,
    const __nv_bfloat16* __restrict__ Bhi, const __nv_bfloat16* __restrict__ Blo,
    const float* __restrict__ bias, const float* __restrict__ resid,
    float* __restrict__ C, __nv_bfloat16* __restrict__ Chi, __nv_bfloat16* __restrict__ Clo,
    int M, int N, int K)
{
    extern __shared__ char smem[];
    const uint32_t sb = smem_u32(smem);

    const int tid = threadIdx.x;
    const int wid = tid >> 5, lane = tid & 31;
    const int warp_m = wid & 1;
    const int warp_n = wid >> 1;
    const int m0 = blockIdx.y * TCBM, n0 = blockIdx.x * TCBN;

    // cp.async segment coordinates (2 segs per plane per thread)
    const int aR0 = tid >> 1, aC0 = (tid & 1) << 1;          // thread covers A rows tid/2, chunks {aC0, aC0+1}
    const int bR0 = tid >> 3, bC0 = (tid & 7) << 1;          // B rows tid/8, chunks {bC0, bC0+1}

    float c[4][4][4];
    #pragma unroll
    for (int i = 0; i < 4; ++i)
        #pragma unroll
        for (int j = 0; j < 4; ++j)
            #pragma unroll
            for (int f = 0; f < 4; ++f) c[i][j][f] = 0.f;

    const uint32_t a_row = (uint32_t)(warp_m * 64 + (lane & 15));
    const uint32_t a_cb  = (uint32_t)((lane >> 4) << 4);
    const uint32_t b_row = (uint32_t)(lane & 15);
    const uint32_t b_cb  = (uint32_t)(warp_n * 64 + ((lane >> 4) << 4));   // bytes

    const int NC = K / TCBK;

    // ---- issue loads for chunk ch into buffer buf ----
    auto issue = [&](int ch, int buf) {
        const uint32_t bb = sb + buf * SM_BUF;
        const int k0 = ch * TCBK;
        #pragma unroll
        for (int i = 0; i < 2; ++i) {
            int r = aR0, ck = aC0 + i;
            size_t g = (size_t)(m0 + r) * K + k0 + ck * 8;
            uint32_t d = bb + r * A_PITCH + ck * 16;
            cp16(d + SM_A_HI, Ahi + g);
            cp16(d + SM_A_LO, Alo + g);
        }
        #pragma unroll
        for (int i = 0; i < 2; ++i) {
            int r = bR0, ck = bC0 + i;
            size_t g = (size_t)(k0 + r) * N + n0 + ck * 8;
            uint32_t d = bb + r * B_PITCH + ck * 16;
            cp16(d + SM_B_HI, Bhi + g);
            cp16(d + SM_B_LO, Blo + g);
        }
        cp_commit();
    };

    issue(0, 0);

    for (int ch = 0; ch < NC; ++ch) {
        const int buf = ch & 1;
        if (ch + 1 < NC) { issue(ch + 1, buf ^ 1); cp_wait1(); }
        else             { cp_wait0(); }
        __syncthreads();

        const uint32_t bb = sb + buf * SM_BUF;
        #pragma unroll
        for (int ks = 0; ks < 2; ++ks) {
            uint32_t bh[4][2], bl[4][2];
            uint32_t b_addr = bb + (b_row + ks * 16) * B_PITCH + b_cb;
            #pragma unroll
            for (int nt2 = 0; nt2 < 2; ++nt2) {
                uint32_t t4[4];
                ldm_x4t(t4, b_addr + SM_B_HI + nt2 * 32);
                bh[nt2 * 2][0] = t4[0]; bh[nt2 * 2][1] = t4[1];
                bh[nt2 * 2 + 1][0] = t4[2]; bh[nt2 * 2 + 1][1] = t4[3];
                ldm_x4t(t4, b_addr + SM_B_LO + nt2 * 32);
                bl[nt2 * 2][0] = t4[0]; bl[nt2 * 2][1] = t4[1];
                bl[nt2 * 2 + 1][0] = t4[2]; bl[nt2 * 2 + 1][1] = t4[3];
            }
            uint32_t a_addr = bb + a_row * A_PITCH + a_cb + ks * 32;
            #pragma unroll
            for (int mt = 0; mt < 4; ++mt) {
                uint32_t ah[4], al[4];
                ldm_x4(ah, a_addr + SM_A_HI + mt * 16 * A_PITCH);
                ldm_x4(al, a_addr + SM_A_LO + mt * 16 * A_PITCH);
                #pragma unroll
                for (int nt = 0; nt < 4; ++nt) {
                    mma_bf16(c[mt][nt], ah, bh[nt]);
                    mma_bf16(c[mt][nt], ah, bl[nt]);
                    mma_bf16(c[mt][nt], al, bh[nt]);
                }
            }
        }
        __syncthreads();
    }

    // ---- epilogue ----
    const int er = lane >> 2, ec = (lane & 3) * 2;
    #pragma unroll
    for (int mt = 0; mt < 4; ++mt) {
        #pragma unroll
        for (int nt = 0; nt < 4; ++nt) {
            int gr = m0 + warp_m * 64 + mt * 16 + er;
            int gc = n0 + warp_n * 32 + nt * 8 + ec;
            #pragma unroll
            for (int half = 0; half < 2; ++half) {
                int row = gr + half * 8;
                float v0 = c[mt][nt][half * 2 + 0];
                float v1 = c[mt][nt][half * 2 + 1];
                if (bias) { v0 += bias[gc]; v1 += bias[gc + 1]; }
                if (resid) {
                    float2 r2 = *(const float2*)(resid + (size_t)row * N + gc);
                    v0 += r2.x; v1 += r2.y;
                }
                if (RELU) { v0 = fmaxf(v0, 0.f); v1 = fmaxf(v1, 0.f); }
                if (SPLIT) {
                    __nv_bfloat16 h0, l0, h1, l1;
                    split1(v0, h0, l0); split1(v1, h1, l1);
                    *(uint32_t*)(Chi + (size_t)row * N + gc) = pack_bf16x2(h0, h1);
                    *(uint32_t*)(Clo + (size_t)row * N + gc) = pack_bf16x2(l0, l1);
                } else {
                    *(float2*)(C + (size_t)row * N + gc) = make_float2(v0, v1);
                }
            }
        }
    }
}

// ---------------- weight convert: fp32 [rows x cols] -> bf16 hi/lo with col offset ----------------
__global__ void conv_w(const float* __restrict__ src, __nv_bfloat16* __restrict__ hi,
                       __nv_bfloat16* __restrict__ lo, int rows, int cols,
                       int dstride, int coff) {
    int idx = blockIdx.x * blockDim.x + threadIdx.x;   // element/4
    int n4 = rows * cols / 4;
    if (idx >= n4) return;
    float4 v = *(const float4*)(src + idx * 4);
    int e = idx * 4;
    int r = e / cols, cc = e % cols;
    __nv_bfloat16 h0, l0, h1, l1, h2, l2, h3, l3;
    split1(v.x, h0, l0); split1(v.y, h1, l1); split1(v.z, h2, l2); split1(v.w, h3, l3);
    size_t d = (size_t)r * dstride + coff + cc;
    *(uint2*)(hi + d) = make_uint2(pack_bf16x2(h0, h1), pack_bf16x2(h2, h3));
    *(uint2*)(lo + d) = make_uint2(pack_bf16x2(l0, l1), pack_bf16x2(l2, l3));
}

// ---------------- block reduction helper ----------------
__device__ __forceinline__ float block_sum_256(float v, float* sred) {
    int lane = threadIdx.x & 31, w = threadIdx.x >> 5;
    #pragma unroll
    for (int o = 16; o; o >>= 1) v += __shfl_xor_sync(0xffffffffu, v, o);
    if (lane == 0) sred[w] = v;
    __syncthreads();
    float r = (threadIdx.x < 8) ? sred[threadIdx.x] : 0.0f;
    if (w == 0) {
        #pragma unroll
        for (int o = 4; o; o >>= 1) r += __shfl_xor_sync(0x000000ffu, r, o);
        if (lane == 0) sred[0] = r;
    }
    __syncthreads();
    float out = sred[0];
    __syncthreads();
    return out;
}

// ---------------- LayerNorm -> bf16 hi/lo ----------------
__global__ void ln_kernel(const float* __restrict__ x, const float* __restrict__ w,
                          const float* __restrict__ b,
                          __nv_bfloat16* __restrict__ ohi, __nv_bfloat16* __restrict__ olo) {
    __shared__ float sred[8];
    size_t row = blockIdx.x;
    const float* xr = x + row * D_MOD;
    float v[4];
    int t = threadIdx.x;
    #pragma unroll
    for (int j = 0; j < 4; ++j) v[j] = xr[t + 256 * j];
    float s = v[0] + v[1] + v[2] + v[3];
    float mu = block_sum_256(s, sred) * (1.0f / D_MOD);
    float d2 = 0.f;
    #pragma unroll
    for (int j = 0; j < 4; ++j) { float d = v[j] - mu; d2 += d * d; }
    float var = block_sum_256(d2, sred) * (1.0f / D_MOD);
    float inv = rsqrtf(var + LN_EPS);
    #pragma unroll
    for (int j = 0; j < 4; ++j) {
        int idx = t + 256 * j;
        float o = (v[j] - mu) * inv * w[idx] + b[idx];
        __nv_bfloat16 h, l;
        split1(o, h, l);
        ohi[row * D_MOD + idx] = h;
        olo[row * D_MOD + idx] = l;
    }
}

// ---------------- Flash attention (causal), fused-QKV input, split ctx output ----------------
#define BQ 64

__global__ __launch_bounds__(256) void attn_kernel(const float* __restrict__ qkv,
                                                   __nv_bfloat16* __restrict__ ctx_hi,
                                                   __nv_bfloat16* __restrict__ ctx_lo) {
    __shared__ float Qs[BQ][HD];
    __shared__ float KP[BQ][HD];
    __shared__ float Vs[BQ][HD];

    int qb = blockIdx.x;
    int bh = blockIdx.y;
    int b  = bh / N_HEAD, h = bh % N_HEAD;
    size_t base = (size_t)b * S_LEN * QKV_N + (size_t)h * HD;
    const float* qp = qkv + base;
    const float* kp = qkv + base + D_MOD;
    const float* vp = qkv + base + 2 * D_MOD;

    int tid  = threadIdx.x;
    int warp = tid >> 5, lane = tid & 31;
    int q8 = warp * 8;
    int k0i = lane, k1i = lane + 32;

    for (int i = tid; i < BQ * HD; i += 256) {
        int r = i >> 6, c = i & 63;
        Qs[r][c] = qp[(size_t)(qb * BQ + r) * QKV_N + c];
    }

    float m[8], lsum[8], acc0[8], acc1[8];
    #pragma unroll
    for (int i = 0; i < 8; ++i) { m[i] = -1e30f; lsum[i] = 0.f; acc0[i] = 0.f; acc1[i] = 0.f; }

    const float scale = 0.125f;
    int ntiles = qb + 1;
    for (int tile = 0; tile < ntiles; ++tile) {
        __syncthreads();
        for (int i = tid; i < BQ * HD; i += 256) {
            int r = i >> 6, c = i & 63;
            KP[r][(c + r) & 63] = kp[(size_t)(tile * BQ + r) * QKV_N + c];
            Vs[r][c]            = vp[(size_t)(tile * BQ + r) * QKV_N + c];
        }
        __syncthreads();

        float s0[8] = {}, s1[8] = {};
        #pragma unroll 4
        for (int d = 0; d < HD; ++d) {
            float kv0 = KP[k0i][(d + k0i) & 63];
            float kv1 = KP[k1i][(d + k1i) & 63];
            #pragma unroll
            for (int qi = 0; qi < 8; ++qi) {
                float qv = Qs[q8 + qi][d];
                s0[qi] += qv * kv0;
                s1[qi] += qv * kv1;
            }
        }

        bool diag = (tile == qb);
        #pragma unroll
        for (int qi = 0; qi < 8; ++qi) {
            float a0 = s0[qi] * scale, a1 = s1[qi] * scale;
            if (diag) {
                int qg = q8 + qi;
                if (k0i > qg) a0 = -1e30f;
                if (k1i > qg) a1 = -1e30f;
            }
            float mx = fmaxf(a0, a1);
            #pragma unroll
            for (int o = 16; o; o >>= 1) mx = fmaxf(mx, __shfl_xor_sync(0xffffffffu, mx, o));
            float mnew = fmaxf(m[qi], mx);
            float corr = __expf(m[qi] - mnew);
            float p0 = __expf(a0 - mnew);
            float p1 = __expf(a1 - mnew);
            float ps = p0 + p1;
            #pragma unroll
            for (int o = 16; o; o >>= 1) ps += __shfl_xor_sync(0xffffffffu, ps, o);
            lsum[qi] = lsum[qi] * corr + ps;
            acc0[qi] *= corr;
            acc1[qi] *= corr;
            m[qi] = mnew;
            s0[qi] = p0; s1[qi] = p1;
        }

        __syncthreads();
        #pragma unroll
        for (int qi = 0; qi < 8; ++qi) {
            KP[q8 + qi][k0i] = s0[qi];
            KP[q8 + qi][k1i] = s1[qi];
        }
        __syncwarp();

        #pragma unroll 4
        for (int kk = 0; kk < BQ; ++kk) {
            float v0 = Vs[kk][k0i];
            float v1 = Vs[kk][k1i];
            #pragma unroll
            for (int qi = 0; qi < 8; ++qi) {
                float p = KP[q8 + qi][kk];
                acc0[qi] += p * v0;
                acc1[qi] += p * v1;
            }
        }
    }

    #pragma unroll
    for (int qi = 0; qi < 8; ++qi) {
        float inv = 1.0f / lsum[qi];
        size_t row = ((size_t)b * S_LEN + qb * BQ + q8 + qi) * D_MOD + (size_t)h * HD;
        float o0 = acc0[qi] * inv, o1 = acc1[qi] * inv;
        __nv_bfloat16 h0, l0, h1, l1;
        split1(o0, h0, l0);
        split1(o1, h1, l1);
        ctx_hi[row + k0i] = h0; ctx_lo[row + k0i] = l0;
        ctx_hi[row + k1i] = h1; ctx_lo[row + k1i] = l1;
    }
}

// ---------------- confidence head ----------------
__global__ void pool_kernel(const float* __restrict__ xo, float* __restrict__ pooled) {
    int idx = blockIdx.x * blockDim.x + threadIdx.x;
    int b = idx >> 10, d = idx & 1023;
    const float* p = xo + (size_t)b * S_LEN * D_MOD + d;
    float s = 0.f;
    #pragma unroll 8
    for (int t = 0; t < S_LEN; ++t) s += p[(size_t)t * D_MOD];
    pooled[idx] = s * (1.0f / S_LEN);
}

__global__ void conf_kernel(const float* __restrict__ pooled, const float* __restrict__ cw,
                            const float* __restrict__ cb, float* __restrict__ out) {
    __shared__ float sred[8];
    float acc[B_SZ] = {};
    for (int d = threadIdx.x; d < D_MOD; d += 256) {
        float w = cw[d];
        #pragma unroll
        for (int b = 0; b < B_SZ; ++b) acc[b] += pooled[b * D_MOD + d] * w;
    }
    float dots[B_SZ];
    #pragma unroll
    for (int b = 0; b < B_SZ; ++b) dots[b] = block_sum_256(acc[b], sred);
    if (threadIdx.x == 0) {
        float s = 0.f;
        #pragma unroll
        for (int b = 0; b < B_SZ; ++b) s += 1.0f / (1.0f + __expf(-(dots[b] + cb[0])));
        out[0] = s * (1.0f / B_SZ);
    }
}

// ---------------- host launch ----------------
template <typename T>
static T* sym(const void* s) {
    void* p = nullptr;
    cudaGetSymbolAddress(&p, s);
    return (T*)p;
}

extern "C" void kernel_launch(void* const* d_in, const int* in_sizes, int n_in,
                              void* d_out, int out_size) {
    const float* x      = (const float*)d_in[0];
    const float* Wq     = (const float*)d_in[1];
    const float* Wk     = (const float*)d_in[2];
    const float* Wv     = (const float*)d_in[3];
    const float* Wo     = (const float*)d_in[4];
    const float* ln1_w  = (const float*)d_in[5];
    const float* ln1_b  = (const float*)d_in[6];
    const float* W1     = (const float*)d_in[7];
    const float* b1     = (const float*)d_in[8];
    const float* W2     = (const float*)d_in[9];
    const float* b2     = (const float*)d_in[10];
    const float* ln2_w  = (const float*)d_in[11];
    const float* ln2_b  = (const float*)d_in[12];
    const float* conf_w = (const float*)d_in[13];
    const float* conf_b = (const float*)d_in[14];
    float* out = (float*)d_out;

    __nv_bfloat16* h_hi   = sym<__nv_bfloat16>(g_h_hi);
    __nv_bfloat16* h_lo   = sym<__nv_bfloat16>(g_h_lo);
    float*         qkv    = sym<float>(g_qkv);
    __nv_bfloat16* ctx_hi = sym<__nv_bfloat16>(g_ctx_hi);
    __nv_bfloat16* ctx_lo = sym<__nv_bfloat16>(g_ctx_lo);
    float*         x1     = sym<float>(g_x1);
    __nv_bfloat16* mid_hi = sym<__nv_bfloat16>(g_mid_hi);
    __nv_bfloat16* mid_lo = sym<__nv_bfloat16>(g_mid_lo);
    float*         pl     = sym<float>(g_pool);
    __nv_bfloat16* wqkv_hi = sym<__nv_bfloat16>(g_wqkv_hi);
    __nv_bfloat16* wqkv_lo = sym<__nv_bfloat16>(g_wqkv_lo);
    __nv_bfloat16* wo_hi  = sym<__nv_bfloat16>(g_wo_hi);
    __nv_bfloat16* wo_lo  = sym<__nv_bfloat16>(g_wo_lo);
    __nv_bfloat16* w1_hi  = sym<__nv_bfloat16>(g_w1_hi);
    __nv_bfloat16* w1_lo  = sym<__nv_bfloat16>(g_w1_lo);
    __nv_bfloat16* w2_hi  = sym<__nv_bfloat16>(g_w2_hi);
    __nv_bfloat16* w2_lo  = sym<__nv_bfloat16>(g_w2_lo);

    cudaFuncSetAttribute(hmma_gemm<false, false>, cudaFuncAttributeMaxDynamicSharedMemorySize, SM_TOT);
    cudaFuncSetAttribute(hmma_gemm<true , true >, cudaFuncAttributeMaxDynamicSharedMemorySize, SM_TOT);

    // ---- weight conversion (cheap elementwise) ----
    {
        int nb = (D_MOD * D_MOD / 4 + 255) / 256;
        conv_w<<<nb, 256>>>(Wq, wqkv_hi, wqkv_lo, D_MOD, D_MOD, QKV_N, 0);
        conv_w<<<nb, 256>>>(Wk, wqkv_hi, wqkv_lo, D_MOD, D_MOD, QKV_N, D_MOD);
        conv_w<<<nb, 256>>>(Wv, wqkv_hi, wqkv_lo, D_MOD, D_MOD, QKV_N, 2 * D_MOD);
        conv_w<<<nb, 256>>>(Wo, wo_hi, wo_lo, D_MOD, D_MOD, D_MOD, 0);
        int nbf = (D_MOD * F_DIM / 4 + 255) / 256;
        conv_w<<<nbf, 256>>>(W1, w1_hi, w1_lo, D_MOD, F_DIM, F_DIM, 0);
        conv_w<<<nbf, 256>>>(W2, w2_hi, w2_lo, F_DIM, D_MOD, D_MOD, 0);
    }

    // LN1 -> split h
    ln_kernel<<<ROWS, 256>>>(x, ln1_w, ln1_b, h_hi, h_lo);
    // fused QKV projection
    dim3 gQKV(QKV_N / TCBN, ROWS / TCBM);   // (24, 64)
    hmma_gemm<false, false><<<gQKV, 256, SM_TOT>>>(h_hi, h_lo, wqkv_hi, wqkv_lo,
        nullptr, nullptr, qkv, nullptr, nullptr, ROWS, QKV_N, D_MOD);
    // causal attention -> split ctx
    dim3 gA(S_LEN / BQ, B_SZ * N_HEAD);
    attn_kernel<<<gA, 256>>>(qkv, ctx_hi, ctx_lo);
    // out-proj + residual
    dim3 gD(D_MOD / TCBN, ROWS / TCBM);     // (8, 64)
    hmma_gemm<false, false><<<gD, 256, SM_TOT>>>(ctx_hi, ctx_lo, wo_hi, wo_lo,
        nullptr, x, x1, nullptr, nullptr, ROWS, D_MOD, D_MOD);
    // LN2 -> split h (reuse)
    ln_kernel<<<ROWS, 256>>>(x1, ln2_w, ln2_b, h_hi, h_lo);
    // FFN1: relu + split out
    dim3 gF(F_DIM / TCBN, ROWS / TCBM);     // (32, 64)
    hmma_gemm<true, true><<<gF, 256, SM_TOT>>>(h_hi, h_lo, w1_hi, w1_lo,
        b1, nullptr, nullptr, mid_hi, mid_lo, ROWS, F_DIM, D_MOD);
    // FFN2: + b2 + resid x1 -> out
    hmma_gemm<false, false><<<gD, 256, SM_TOT>>>(mid_hi, mid_lo, w2_hi, w2_lo,
        b2, x1, out, nullptr, nullptr, ROWS, D_MOD, F_DIM);
    // confidence head
    pool_kernel<<<16, 256>>>(out, pl);
    conf_kernel<<<1, 256>>>(pl, conf_w, conf_b, out + (out_size - 1));
}

// round 5
// speedup vs baseline: 2.7796x; 1.3958x over previous
#include <cuda_runtime.h>
#include <cuda_bf16.h>
#include <cstdint>

// Problem constants
#define B_SZ   4
#define S_LEN  2048
#define D_MOD  1024
#define F_DIM  4096
#define N_HEAD 16
#define HD     64
#define ROWS   (B_SZ * S_LEN)        // 8192
#define QKV_N  (3 * D_MOD)           // 3072
#define LN_EPS 1e-5f

// ---------------- scratch (device globals; no allocation) ----------------
__device__ __nv_bfloat16 g_h_hi [ROWS * D_MOD];
__device__ __nv_bfloat16 g_h_lo [ROWS * D_MOD];
__device__ __nv_bfloat16 g_qkv_hi[ROWS * QKV_N];
__device__ __nv_bfloat16 g_qkv_lo[ROWS * QKV_N];
__device__ __nv_bfloat16 g_ctx_hi[ROWS * D_MOD];
__device__ __nv_bfloat16 g_ctx_lo[ROWS * D_MOD];
__device__ float         g_x1  [ROWS * D_MOD];
__device__ __nv_bfloat16 g_mid_hi[ROWS * F_DIM];
__device__ __nv_bfloat16 g_mid_lo[ROWS * F_DIM];
__device__ float         g_pool[B_SZ * D_MOD];
__device__ __nv_bfloat16 g_wqkv_hi[D_MOD * QKV_N];
__device__ __nv_bfloat16 g_wqkv_lo[D_MOD * QKV_N];
__device__ __nv_bfloat16 g_wo_hi [D_MOD * D_MOD];
__device__ __nv_bfloat16 g_wo_lo [D_MOD * D_MOD];
__device__ __nv_bfloat16 g_w1_hi [D_MOD * F_DIM];
__device__ __nv_bfloat16 g_w1_lo [D_MOD * F_DIM];
__device__ __nv_bfloat16 g_w2_hi [F_DIM * D_MOD];
__device__ __nv_bfloat16 g_w2_lo [F_DIM * D_MOD];

// ======================= helpers =======================
__device__ __forceinline__ uint32_t smem_u32(const void* p) {
    uint32_t a;
    asm("{ .reg .u64 t; cvta.to.shared.u64 t, %1; cvt.u32.u64 %0, t; }" : "=r"(a) : "l"(p));
    return a;
}
__device__ __forceinline__ void ldm_x4(uint32_t* r, uint32_t addr) {
    asm volatile("ldmatrix.sync.aligned.m8n8.x4.shared.b16 {%0,%1,%2,%3}, [%4];"
        : "=r"(r[0]), "=r"(r[1]), "=r"(r[2]), "=r"(r[3]) : "r"(addr));
}
__device__ __forceinline__ void ldm_x4t(uint32_t* r, uint32_t addr) {
    asm volatile("ldmatrix.sync.aligned.m8n8.x4.trans.shared.b16 {%0,%1,%2,%3}, [%4];"
        : "=r"(r[0]), "=r"(r[1]), "=r"(r[2]), "=r"(r[3]) : "r"(addr));
}
__device__ __forceinline__ void mma_bf16(float* c, const uint32_t* a, const uint32_t* b) {
    asm volatile(
        "mma.sync.aligned.m16n8k16.row.col.f32.bf16.bf16.f32 "
        "{%0,%1,%2,%3}, {%4,%5,%6,%7}, {%8,%9}, {%0,%1,%2,%3};"
        : "+f"(c[0]), "+f"(c[1]), "+f"(c[2]), "+f"(c[3])
        : "r"(a[0]), "r"(a[1]), "r"(a[2]), "r"(a[3]), "r"(b[0]), "r"(b[1]));
}
__device__ __forceinline__ void cp16(uint32_t dst, const void* src) {
    asm volatile("cp.async.cg.shared.global [%0], [%1], 16;" :: "r"(dst), "l"(src));
}
__device__ __forceinline__ void cp_commit() { asm volatile("cp.async.commit_group;" ::: "memory"); }
__device__ __forceinline__ void cp_wait1()  { asm volatile("cp.async.wait_group 1;" ::: "memory"); }
__device__ __forceinline__ void cp_wait0()  { asm volatile("cp.async.wait_group 0;" ::: "memory"); }
__device__ __forceinline__ uint32_t pack_bf16x2(__nv_bfloat16 a, __nv_bfloat16 b) {
    __nv_bfloat162 v; v.x = a; v.y = b;
    return *reinterpret_cast<uint32_t*>(&v);
}
__device__ __forceinline__ void split1(float x, __nv_bfloat16& h, __nv_bfloat16& l) {
    h = __float2bfloat16(x);
    l = __float2bfloat16(x - __bfloat162float(h));
}

// ======================= pipelined HMMA GEMM =======================
#define TCBM 128
#define TCBN 128
#define TCBK 32
#define A_PITCH 80
#define B_PITCH 272
#define SM_A_HI 0
#define SM_A_LO 10240
#define SM_B_HI 20480
#define SM_B_LO 29184
#define SM_BUF  37888
#define SM_TOT  (2 * SM_BUF)

template <bool RELU, bool SPLIT>
__global__ __launch_bounds__(256, 2) void hmma_gemm(
    const __nv_bfloat16* __restrict__ Ahi, const __nv_bfloat16* __restrict__ Alo,
    const __nv_bfloat16* __restrict__ Bhi, const __nv_bfloat16* __restrict__ Blo,
    const float* __restrict__ bias, const float* __restrict__ resid,
    float* __restrict__ C, __nv_bfloat16* __restrict__ Chi, __nv_bfloat16* __restrict__ Clo,
    int M, int N, int K)
{
    extern __shared__ char smem[];
    const uint32_t sb = smem_u32(smem);

    const int tid = threadIdx.x;
    const int wid = tid >> 5, lane = tid & 31;
    const int warp_m = wid & 1;
    const int warp_n = wid >> 1;
    const int m0 = blockIdx.y * TCBM, n0 = blockIdx.x * TCBN;

    const int aR0 = tid >> 1, aC0 = (tid & 1) << 1;
    const int bR0 = tid >> 3, bC0 = (tid & 7) << 1;

    float c[4][4][4];
    #pragma unroll
    for (int i = 0; i < 4; ++i)
        #pragma unroll
        for (int j = 0; j < 4; ++j)
            #pragma unroll
            for (int f = 0; f < 4; ++f) c[i][j][f] = 0.f;

    const uint32_t a_row = (uint32_t)(warp_m * 64 + (lane & 15));
    const uint32_t a_cb  = (uint32_t)((lane >> 4) << 4);
    const uint32_t b_row = (uint32_t)(lane & 15);
    const uint32_t b_cb  = (uint32_t)(warp_n * 64 + ((lane >> 4) << 4));

    const int NC = K / TCBK;

    auto issue = [&](int ch, int buf) {
        const uint32_t bb = sb + buf * SM_BUF;
        const int k0 = ch * TCBK;
        #pragma unroll
        for (int i = 0; i < 2; ++i) {
            int r = aR0, ck = aC0 + i;
            size_t g = (size_t)(m0 + r) * K + k0 + ck * 8;
            uint32_t d = bb + r * A_PITCH + ck * 16;
            cp16(d + SM_A_HI, Ahi + g);
            cp16(d + SM_A_LO, Alo + g);
        }
        #pragma unroll
        for (int i = 0; i < 2; ++i) {
            int r = bR0, ck = bC0 + i;
            size_t g = (size_t)(k0 + r) * N + n0 + ck * 8;
            uint32_t d = bb + r * B_PITCH + ck * 16;
            cp16(d + SM_B_HI, Bhi + g);
            cp16(d + SM_B_LO, Blo + g);
        }
        cp_commit();
    };

    issue(0, 0);

    for (int ch = 0; ch < NC; ++ch) {
        const int buf = ch & 1;
        if (ch + 1 < NC) { issue(ch + 1, buf ^ 1); cp_wait1(); }
        else             { cp_wait0(); }
        __syncthreads();

        const uint32_t bb = sb + buf * SM_BUF;
        #pragma unroll
        for (int ks = 0; ks < 2; ++ks) {
            uint32_t bh[4][2], bl[4][2];
            uint32_t b_addr = bb + (b_row + ks * 16) * B_PITCH + b_cb;
            #pragma unroll
            for (int nt2 = 0; nt2 < 2; ++nt2) {
                uint32_t t4[4];
                ldm_x4t(t4, b_addr + SM_B_HI + nt2 * 32);
                bh[nt2 * 2][0] = t4[0]; bh[nt2 * 2][1] = t4[1];
                bh[nt2 * 2 + 1][0] = t4[2]; bh[nt2 * 2 + 1][1] = t4[3];
                ldm_x4t(t4, b_addr + SM_B_LO + nt2 * 32);
                bl[nt2 * 2][0] = t4[0]; bl[nt2 * 2][1] = t4[1];
                bl[nt2 * 2 + 1][0] = t4[2]; bl[nt2 * 2 + 1][1] = t4[3];
            }
            uint32_t a_addr = bb + a_row * A_PITCH + a_cb + ks * 32;
            #pragma unroll
            for (int mt = 0; mt < 4; ++mt) {
                uint32_t ah[4], al[4];
                ldm_x4(ah, a_addr + SM_A_HI + mt * 16 * A_PITCH);
                ldm_x4(al, a_addr + SM_A_LO + mt * 16 * A_PITCH);
                #pragma unroll
                for (int nt = 0; nt < 4; ++nt) {
                    mma_bf16(c[mt][nt], ah, bh[nt]);
                    mma_bf16(c[mt][nt], ah, bl[nt]);
                    mma_bf16(c[mt][nt], al, bh[nt]);
                }
            }
        }
        __syncthreads();
    }

    const int er = lane >> 2, ec = (lane & 3) * 2;
    #pragma unroll
    for (int mt = 0; mt < 4; ++mt) {
        #pragma unroll
        for (int nt = 0; nt < 4; ++nt) {
            int gr = m0 + warp_m * 64 + mt * 16 + er;
            int gc = n0 + warp_n * 32 + nt * 8 + ec;
            #pragma unroll
            for (int half = 0; half < 2; ++half) {
                int row = gr + half * 8;
                float v0 = c[mt][nt][half * 2 + 0];
                float v1 = c[mt][nt][half * 2 + 1];
                if (bias) { v0 += bias[gc]; v1 += bias[gc + 1]; }
                if (resid) {
                    float2 r2 = *(const float2*)(resid + (size_t)row * N + gc);
                    v0 += r2.x; v1 += r2.y;
                }
                if (RELU) { v0 = fmaxf(v0, 0.f); v1 = fmaxf(v1, 0.f); }
                if (SPLIT) {
                    __nv_bfloat16 h0, l0, h1, l1;
                    split1(v0, h0, l0); split1(v1, h1, l1);
                    *(uint32_t*)(Chi + (size_t)row * N + gc) = pack_bf16x2(h0, h1);
                    *(uint32_t*)(Clo + (size_t)row * N + gc) = pack_bf16x2(l0, l1);
                } else {
                    *(float2*)(C + (size_t)row * N + gc) = make_float2(v0, v1);
                }
            }
        }
    }
}

// ---------------- weight convert ----------------
__global__ void conv_w(const float* __restrict__ src, __nv_bfloat16* __restrict__ hi,
                       __nv_bfloat16* __restrict__ lo, int rows, int cols,
                       int dstride, int coff) {
    int idx = blockIdx.x * blockDim.x + threadIdx.x;
    int n4 = rows * cols / 4;
    if (idx >= n4) return;
    float4 v = *(const float4*)(src + idx * 4);
    int e = idx * 4;
    int r = e / cols, cc = e % cols;
    __nv_bfloat16 h0, l0, h1, l1, h2, l2, h3, l3;
    split1(v.x, h0, l0); split1(v.y, h1, l1); split1(v.z, h2, l2); split1(v.w, h3, l3);
    size_t d = (size_t)r * dstride + coff + cc;
    *(uint2*)(hi + d) = make_uint2(pack_bf16x2(h0, h1), pack_bf16x2(h2, h3));
    *(uint2*)(lo + d) = make_uint2(pack_bf16x2(l0, l1), pack_bf16x2(l2, l3));
}

// ---------------- block reduction helper ----------------
__device__ __forceinline__ float block_sum_256(float v, float* sred) {
    int lane = threadIdx.x & 31, w = threadIdx.x >> 5;
    #pragma unroll
    for (int o = 16; o; o >>= 1) v += __shfl_xor_sync(0xffffffffu, v, o);
    if (lane == 0) sred[w] = v;
    __syncthreads();
    float r = (threadIdx.x < 8) ? sred[threadIdx.x] : 0.0f;
    if (w == 0) {
        #pragma unroll
        for (int o = 4; o; o >>= 1) r += __shfl_xor_sync(0x000000ffu, r, o);
        if (lane == 0) sred[0] = r;
    }
    __syncthreads();
    float out = sred[0];
    __syncthreads();
    return out;
}

// ---------------- LayerNorm -> bf16 hi/lo ----------------
__global__ void ln_kernel(const float* __restrict__ x, const float* __restrict__ w,
                          const float* __restrict__ b,
                          __nv_bfloat16* __restrict__ ohi, __nv_bfloat16* __restrict__ olo) {
    __shared__ float sred[8];
    size_t row = blockIdx.x;
    const float* xr = x + row * D_MOD;
    float v[4];
    int t = threadIdx.x;
    #pragma unroll
    for (int j = 0; j < 4; ++j) v[j] = xr[t + 256 * j];
    float s = v[0] + v[1] + v[2] + v[3];
    float mu = block_sum_256(s, sred) * (1.0f / D_MOD);
    float d2 = 0.f;
    #pragma unroll
    for (int j = 0; j < 4; ++j) { float d = v[j] - mu; d2 += d * d; }
    float var = block_sum_256(d2, sred) * (1.0f / D_MOD);
    float inv = rsqrtf(var + LN_EPS);
    #pragma unroll
    for (int j = 0; j < 4; ++j) {
        int idx = t + 256 * j;
        float o = (v[j] - mu) * inv * w[idx] + b[idx];
        __nv_bfloat16 h, l;
        split1(o, h, l);
        ohi[row * D_MOD + idx] = h;
        olo[row * D_MOD + idx] = l;
    }
}

// ======================= MMA flash attention (causal) =======================
// Block: 128 threads (4 warps), 64 queries (16 per warp); key tiles of 64.
// S via 3-term split MMA; softmax fp32 in fragments; P split in regs; PV 3-term MMA.
#define AQ 64
#define APITCH 144
#define ASM_Q_HI 0
#define ASM_Q_LO (64 * APITCH)               //  9216
#define ASM_K_HI (2 * 64 * APITCH)           // 18432
#define ASM_K_LO (3 * 64 * APITCH)
#define ASM_V_HI (4 * 64 * APITCH)
#define ASM_V_LO (5 * 64 * APITCH)
#define ASM_TOT  (6 * 64 * APITCH)           // 55296

__global__ __launch_bounds__(128) void attn_mma(
    const __nv_bfloat16* __restrict__ qkv_hi, const __nv_bfloat16* __restrict__ qkv_lo,
    __nv_bfloat16* __restrict__ ctx_hi, __nv_bfloat16* __restrict__ ctx_lo)
{
    extern __shared__ char sm[];
    const uint32_t sb = smem_u32(sm);
    const int qb = blockIdx.x;
    const int bh = blockIdx.y;
    const int b = bh >> 4, h = bh & 15;
    const int tid = threadIdx.x, w = tid >> 5, lane = tid & 31;
    const size_t tok0 = (size_t)b * S_LEN;
    const int q0 = qb * AQ;
    const int hcol = h * HD;

    // ---- load Q tile (hi/lo) ----
    #pragma unroll
    for (int i = 0; i < 4; ++i) {
        int idx = i * 128 + tid;           // 512 chunks/plane
        int r = idx >> 3, ck = idx & 7;
        size_t g = (tok0 + q0 + r) * QKV_N + hcol + ck * 8;
        cp16(sb + ASM_Q_HI + r * APITCH + ck * 16, qkv_hi + g);
        cp16(sb + ASM_Q_LO + r * APITCH + ck * 16, qkv_lo + g);
    }
    cp_commit(); cp_wait0();
    __syncthreads();

    // ---- Q fragments (held in registers for whole kernel) ----
    uint32_t qh[4][4], ql[4][4];
    {
        uint32_t base = sb + (uint32_t)(w * 16 + (lane & 15)) * APITCH + ((lane >> 4) << 4);
        #pragma unroll
        for (int kt = 0; kt < 4; ++kt) {
            ldm_x4(qh[kt], base + ASM_Q_HI + kt * 32);
            ldm_x4(ql[kt], base + ASM_Q_LO + kt * 32);
        }
    }

    float o[8][4];
    #pragma unroll
    for (int nt = 0; nt < 8; ++nt)
        #pragma unroll
        for (int f = 0; f < 4; ++f) o[nt][f] = 0.f;
    float m0 = -1e30f, m1 = -1e30f, l0 = 0.f, l1 = 0.f;

    const uint32_t krow = (uint32_t)((lane & 7) + ((lane >> 4) << 3));
    const uint32_t kcb  = (uint32_t)(((lane >> 3) & 1) << 4);

    const int ntiles = qb + 1;
    for (int t = 0; t < ntiles; ++t) {
        __syncthreads();
        // ---- load K/V tile (hi/lo) ----
        #pragma unroll
        for (int i = 0; i < 4; ++i) {
            int idx = i * 128 + tid;
            int r = idx >> 3, ck = idx & 7;
            size_t gk = (tok0 + t * 64 + r) * QKV_N + hcol + D_MOD + ck * 8;
            uint32_t off = (uint32_t)(r * APITCH + ck * 16);
            cp16(sb + ASM_K_HI + off, qkv_hi + gk);
            cp16(sb + ASM_K_LO + off, qkv_lo + gk);
            cp16(sb + ASM_V_HI + off, qkv_hi + gk + D_MOD);
            cp16(sb + ASM_V_LO + off, qkv_lo + gk + D_MOD);
        }
        cp_commit(); cp_wait0();
        __syncthreads();

        // ---- S = Q K^T (3-term) ----
        float s[8][4];
        #pragma unroll
        for (int nt = 0; nt < 8; ++nt)
            #pragma unroll
            for (int f = 0; f < 4; ++f) s[nt][f] = 0.f;

        #pragma unroll
        for (int kt = 0; kt < 4; ++kt) {
            uint32_t kh[8][2], kl[8][2];
            uint32_t kaddr = sb + krow * APITCH + kcb + kt * 32;
            #pragma unroll
            for (int p = 0; p < 4; ++p) {
                uint32_t t4[4];
                ldm_x4(t4, kaddr + ASM_K_HI + p * 16 * APITCH);
                kh[2 * p][0] = t4[0]; kh[2 * p][1] = t4[1];
                kh[2 * p + 1][0] = t4[2]; kh[2 * p + 1][1] = t4[3];
                ldm_x4(t4, kaddr + ASM_K_LO + p * 16 * APITCH);
                kl[2 * p][0] = t4[0]; kl[2 * p][1] = t4[1];
                kl[2 * p + 1][0] = t4[2]; kl[2 * p + 1][1] = t4[3];
            }
            #pragma unroll
            for (int nt = 0; nt < 8; ++nt) {
                mma_bf16(s[nt], qh[kt], kh[nt]);
                mma_bf16(s[nt], qh[kt], kl[nt]);
                mma_bf16(s[nt], ql[kt], kh[nt]);
            }
        }

        // ---- scale + causal mask ----
        #pragma unroll
        for (int nt = 0; nt < 8; ++nt)
            #pragma unroll
            for (int f = 0; f < 4; ++f) s[nt][f] *= 0.125f;
        if (t == qb) {
            int r0 = w * 16 + (lane >> 2);
            int r1 = r0 + 8;
            #pragma unroll
            for (int nt = 0; nt < 8; ++nt) {
                int c0 = nt * 8 + (lane & 3) * 2;
                if (c0     > r0) s[nt][0] = -1e30f;
                if (c0 + 1 > r0) s[nt][1] = -1e30f;
                if (c0     > r1) s[nt][2] = -1e30f;
                if (c0 + 1 > r1) s[nt][3] = -1e30f;
            }
        }

        // ---- online softmax ----
        float mx0 = -1e30f, mx1 = -1e30f;
        #pragma unroll
        for (int nt = 0; nt < 8; ++nt) {
            mx0 = fmaxf(mx0, fmaxf(s[nt][0], s[nt][1]));
            mx1 = fmaxf(mx1, fmaxf(s[nt][2], s[nt][3]));
        }
        #pragma unroll
        for (int ofs = 1; ofs <= 2; ofs <<= 1) {
            mx0 = fmaxf(mx0, __shfl_xor_sync(0xffffffffu, mx0, ofs));
            mx1 = fmaxf(mx1, __shfl_xor_sync(0xffffffffu, mx1, ofs));
        }
        float mn0 = fmaxf(m0, mx0), mn1 = fmaxf(m1, mx1);
        float cr0 = __expf(m0 - mn0), cr1 = __expf(m1 - mn1);
        float ps0 = 0.f, ps1 = 0.f;
        #pragma unroll
        for (int nt = 0; nt < 8; ++nt) {
            s[nt][0] = __expf(s[nt][0] - mn0);
            s[nt][1] = __expf(s[nt][1] - mn0);
            s[nt][2] = __expf(s[nt][2] - mn1);
            s[nt][3] = __expf(s[nt][3] - mn1);
            ps0 += s[nt][0] + s[nt][1];
            ps1 += s[nt][2] + s[nt][3];
        }
        #pragma unroll
        for (int ofs = 1; ofs <= 2; ofs <<= 1) {
            ps0 += __shfl_xor_sync(0xffffffffu, ps0, ofs);
            ps1 += __shfl_xor_sync(0xffffffffu, ps1, ofs);
        }
        l0 = l0 * cr0 + ps0;
        l1 = l1 * cr1 + ps1;
        m0 = mn0; m1 = mn1;
        #pragma unroll
        for (int nt = 0; nt < 8; ++nt) {
            o[nt][0] *= cr0; o[nt][1] *= cr0;
            o[nt][2] *= cr1; o[nt][3] *= cr1;
        }

        // ---- pack P into A-operand fragments (hi/lo) ----
        uint32_t ph[4][4], pl[4][4];
        #pragma unroll
        for (int t2 = 0; t2 < 4; ++t2) {
            __nv_bfloat16 hh[8], ll[8];
            #pragma unroll
            for (int j = 0; j < 4; ++j) {
                split1(s[2 * t2][j], hh[j], ll[j]);
                split1(s[2 * t2 + 1][j], hh[4 + j], ll[4 + j]);
            }
            ph[t2][0] = pack_bf16x2(hh[0], hh[1]); ph[t2][1] = pack_bf16x2(hh[2], hh[3]);
            ph[t2][2] = pack_bf16x2(hh[4], hh[5]); ph[t2][3] = pack_bf16x2(hh[6], hh[7]);
            pl[t2][0] = pack_bf16x2(ll[0], ll[1]); pl[t2][1] = pack_bf16x2(ll[2], ll[3]);
            pl[t2][2] = pack_bf16x2(ll[4], ll[5]); pl[t2][3] = pack_bf16x2(ll[6], ll[7]);
        }

        // ---- O += P V (3-term) ----
        #pragma unroll
        for (int kt2 = 0; kt2 < 4; ++kt2) {
            uint32_t vh[8][2], vl[8][2];
            uint32_t vaddr = sb + (uint32_t)(kt2 * 16 + (lane & 15)) * APITCH + ((lane >> 4) << 4);
            #pragma unroll
            for (int p = 0; p < 4; ++p) {
                uint32_t t4[4];
                ldm_x4t(t4, vaddr + ASM_V_HI + p * 32);
                vh[2 * p][0] = t4[0]; vh[2 * p][1] = t4[1];
                vh[2 * p + 1][0] = t4[2]; vh[2 * p + 1][1] = t4[3];
                ldm_x4t(t4, vaddr + ASM_V_LO + p * 32);
                vl[2 * p][0] = t4[0]; vl[2 * p][1] = t4[1];
                vl[2 * p + 1][0] = t4[2]; vl[2 * p + 1][1] = t4[3];
            }
            #pragma unroll
            for (int nt = 0; nt < 8; ++nt) {
                mma_bf16(o[nt], ph[kt2], vh[nt]);
                mma_bf16(o[nt], ph[kt2], vl[nt]);
                mma_bf16(o[nt], pl[kt2], vh[nt]);
            }
        }
    }

    // ---- write ctx (split) ----
    float i0 = 1.0f / l0, i1 = 1.0f / l1;
    size_t gr0 = tok0 + q0 + w * 16 + (lane >> 2);
    size_t gr1 = gr0 + 8;
    #pragma unroll
    for (int nt = 0; nt < 8; ++nt) {
        int col = hcol + nt * 8 + (lane & 3) * 2;
        float v0 = o[nt][0] * i0, v1 = o[nt][1] * i0;
        float v2 = o[nt][2] * i1, v3 = o[nt][3] * i1;
        __nv_bfloat16 h0, lo0, h1, lo1, h2, lo2, h3, lo3;
        split1(v0, h0, lo0); split1(v1, h1, lo1);
        split1(v2, h2, lo2); split1(v3, h3, lo3);
        *(uint32_t*)(ctx_hi + gr0 * D_MOD + col) = pack_bf16x2(h0, h1);
        *(uint32_t*)(ctx_lo + gr0 * D_MOD + col) = pack_bf16x2(lo0, lo1);
        *(uint32_t*)(ctx_hi + gr1 * D_MOD + col) = pack_bf16x2(h2, h3);
        *(uint32_t*)(ctx_lo + gr1 * D_MOD + col) = pack_bf16x2(lo2, lo3);
    }
}

// ---------------- confidence head ----------------
__global__ void pool_kernel(const float* __restrict__ xo, float* __restrict__ pooled) {
    int idx = blockIdx.x * blockDim.x + threadIdx.x;
    int b = idx >> 10, d = idx & 1023;
    const float* p = xo + (size_t)b * S_LEN * D_MOD + d;
    float s = 0.f;
    #pragma unroll 8
    for (int t = 0; t < S_LEN; ++t) s += p[(size_t)t * D_MOD];
    pooled[idx] = s * (1.0f / S_LEN);
}

__global__ void conf_kernel(const float* __restrict__ pooled, const float* __restrict__ cw,
                            const float* __restrict__ cb, float* __restrict__ out) {
    __shared__ float sred[8];
    float acc[B_SZ] = {};
    for (int d = threadIdx.x; d < D_MOD; d += 256) {
        float w = cw[d];
        #pragma unroll
        for (int b = 0; b < B_SZ; ++b) acc[b] += pooled[b * D_MOD + d] * w;
    }
    float dots[B_SZ];
    #pragma unroll
    for (int b = 0; b < B_SZ; ++b) dots[b] = block_sum_256(acc[b], sred);
    if (threadIdx.x == 0) {
        float s = 0.f;
        #pragma unroll
        for (int b = 0; b < B_SZ; ++b) s += 1.0f / (1.0f + __expf(-(dots[b] + cb[0])));
        out[0] = s * (1.0f / B_SZ);
    }
}

// ---------------- host launch ----------------
template <typename T>
static T* sym(const void* s) {
    void* p = nullptr;
    cudaGetSymbolAddress(&p, s);
    return (T*)p;
}

extern "C" void kernel_launch(void* const* d_in, const int* in_sizes, int n_in,
                              void* d_out, int out_size) {
    const float* x      = (const float*)d_in[0];
    const float* Wq     = (const float*)d_in[1];
    const float* Wk     = (const float*)d_in[2];
    const float* Wv     = (const float*)d_in[3];
    const float* Wo     = (const float*)d_in[4];
    const float* ln1_w  = (const float*)d_in[5];
    const float* ln1_b  = (const float*)d_in[6];
    const float* W1     = (const float*)d_in[7];
    const float* b1     = (const float*)d_in[8];
    const float* W2     = (const float*)d_in[9];
    const float* b2     = (const float*)d_in[10];
    const float* ln2_w  = (const float*)d_in[11];
    const float* ln2_b  = (const float*)d_in[12];
    const float* conf_w = (const float*)d_in[13];
    const float* conf_b = (const float*)d_in[14];
    float* out = (float*)d_out;

    __nv_bfloat16* h_hi   = sym<__nv_bfloat16>(g_h_hi);
    __nv_bfloat16* h_lo   = sym<__nv_bfloat16>(g_h_lo);
    __nv_bfloat16* qkv_hi = sym<__nv_bfloat16>(g_qkv_hi);
    __nv_bfloat16* qkv_lo = sym<__nv_bfloat16>(g_qkv_lo);
    __nv_bfloat16* ctx_hi = sym<__nv_bfloat16>(g_ctx_hi);
    __nv_bfloat16* ctx_lo = sym<__nv_bfloat16>(g_ctx_lo);
    float*         x1     = sym<float>(g_x1);
    __nv_bfloat16* mid_hi = sym<__nv_bfloat16>(g_mid_hi);
    __nv_bfloat16* mid_lo = sym<__nv_bfloat16>(g_mid_lo);
    float*         pl     = sym<float>(g_pool);
    __nv_bfloat16* wqkv_hi = sym<__nv_bfloat16>(g_wqkv_hi);
    __nv_bfloat16* wqkv_lo = sym<__nv_bfloat16>(g_wqkv_lo);
    __nv_bfloat16* wo_hi  = sym<__nv_bfloat16>(g_wo_hi);
    __nv_bfloat16* wo_lo  = sym<__nv_bfloat16>(g_wo_lo);
    __nv_bfloat16* w1_hi  = sym<__nv_bfloat16>(g_w1_hi);
    __nv_bfloat16* w1_lo  = sym<__nv_bfloat16>(g_w1_lo);
    __nv_bfloat16* w2_hi  = sym<__nv_bfloat16>(g_w2_hi);
    __nv_bfloat16* w2_lo  = sym<__nv_bfloat16>(g_w2_lo);

    cudaFuncSetAttribute(hmma_gemm<false, false>, cudaFuncAttributeMaxDynamicSharedMemorySize, SM_TOT);
    cudaFuncSetAttribute(hmma_gemm<false, true >, cudaFuncAttributeMaxDynamicSharedMemorySize, SM_TOT);
    cudaFuncSetAttribute(hmma_gemm<true , true >, cudaFuncAttributeMaxDynamicSharedMemorySize, SM_TOT);
    cudaFuncSetAttribute(attn_mma, cudaFuncAttributeMaxDynamicSharedMemorySize, ASM_TOT);

    // ---- weight conversion ----
    {
        int nb = (D_MOD * D_MOD / 4 + 255) / 256;
        conv_w<<<nb, 256>>>(Wq, wqkv_hi, wqkv_lo, D_MOD, D_MOD, QKV_N, 0);
        conv_w<<<nb, 256>>>(Wk, wqkv_hi, wqkv_lo, D_MOD, D_MOD, QKV_N, D_MOD);
        conv_w<<<nb, 256>>>(Wv, wqkv_hi, wqkv_lo, D_MOD, D_MOD, QKV_N, 2 * D_MOD);
        conv_w<<<nb, 256>>>(Wo, wo_hi, wo_lo, D_MOD, D_MOD, D_MOD, 0);
        int nbf = (D_MOD * F_DIM / 4 + 255) / 256;
        conv_w<<<nbf, 256>>>(W1, w1_hi, w1_lo, D_MOD, F_DIM, F_DIM, 0);
        conv_w<<<nbf, 256>>>(W2, w2_hi, w2_lo, F_DIM, D_MOD, D_MOD, 0);
    }

    // LN1 -> split h
    ln_kernel<<<ROWS, 256>>>(x, ln1_w, ln1_b, h_hi, h_lo);
    // fused QKV projection -> split bf16 output
    dim3 gQKV(QKV_N / TCBN, ROWS / TCBM);
    hmma_gemm<false, true><<<gQKV, 256, SM_TOT>>>(h_hi, h_lo, wqkv_hi, wqkv_lo,
        nullptr, nullptr, nullptr, qkv_hi, qkv_lo, ROWS, QKV_N, D_MOD);
    // causal attention (MMA) -> split ctx
    dim3 gA(S_LEN / AQ, B_SZ * N_HEAD);    // (32, 64)
    attn_mma<<<gA, 128, ASM_TOT>>>(qkv_hi, qkv_lo, ctx_hi, ctx_lo);
    // out-proj + residual
    dim3 gD(D_MOD / TCBN, ROWS / TCBM);
    hmma_gemm<false, false><<<gD, 256, SM_TOT>>>(ctx_hi, ctx_lo, wo_hi, wo_lo,
        nullptr, x, x1, nullptr, nullptr, ROWS, D_MOD, D_MOD);
    // LN2 -> split h
    ln_kernel<<<ROWS, 256>>>(x1, ln2_w, ln2_b, h_hi, h_lo);
    // FFN1
    dim3 gF(F_DIM / TCBN, ROWS / TCBM);
    hmma_gemm<true, true><<<gF, 256, SM_TOT>>>(h_hi, h_lo, w1_hi, w1_lo,
        b1, nullptr, nullptr, mid_hi, mid_lo, ROWS, F_DIM, D_MOD);
    // FFN2
    hmma_gemm<false, false><<<gD, 256, SM_TOT>>>(mid_hi, mid_lo, w2_hi, w2_lo,
        b2, x1, out, nullptr, nullptr, ROWS, D_MOD, F_DIM);
    // confidence head
    pool_kernel<<<16, 256>>>(out, pl);
    conf_kernel<<<1, 256>>>(pl, conf_w, conf_b, out + (out_size - 1));
}

// round 6
// speedup vs baseline: 3.6221x; 1.3031x over previous
#include <cuda_runtime.h>
#include <cuda_bf16.h>
#include <cuda_fp16.h>
#include <cstdint>

// Problem constants
#define B_SZ   4
#define S_LEN  2048
#define D_MOD  1024
#define F_DIM  4096
#define N_HEAD 16
#define HD     64
#define ROWS   (B_SZ * S_LEN)        // 8192
#define QKV_N  (3 * D_MOD)           // 3072
#define LN_EPS 1e-5f

// ---------------- scratch (device globals; no allocation) ----------------
__device__ __half g_h_hi [ROWS * D_MOD];
__device__ __half g_h_lo [ROWS * D_MOD];
__device__ __half g_qkv_hi[ROWS * QKV_N];
__device__ __half g_qkv_lo[ROWS * QKV_N];
__device__ __half g_ctx_hi[ROWS * D_MOD];
__device__ __half g_ctx_lo[ROWS * D_MOD];
__device__ float  g_x1  [ROWS * D_MOD];
__device__ __half g_mid_hi[ROWS * F_DIM];
__device__ __half g_mid_lo[ROWS * F_DIM];
__device__ float  g_pool[B_SZ * D_MOD];
// converted weights (B-side: fp16 hi only)
__device__ __half g_wqkv_hi[D_MOD * QKV_N];
__device__ __half g_wo_hi [D_MOD * D_MOD];
__device__ __half g_w1_hi [D_MOD * F_DIM];
__device__ __half g_w2_hi [F_DIM * D_MOD];

// ======================= helpers =======================
__device__ __forceinline__ uint32_t smem_u32(const void* p) {
    uint32_t a;
    asm("{ .reg .u64 t; cvta.to.shared.u64 t, %1; cvt.u32.u64 %0, t; }" : "=r"(a) : "l"(p));
    return a;
}
__device__ __forceinline__ void ldm_x4(uint32_t* r, uint32_t addr) {
    asm volatile("ldmatrix.sync.aligned.m8n8.x4.shared.b16 {%0,%1,%2,%3}, [%4];"
        : "=r"(r[0]), "=r"(r[1]), "=r"(r[2]), "=r"(r[3]) : "r"(addr));
}
__device__ __forceinline__ void ldm_x4t(uint32_t* r, uint32_t addr) {
    asm volatile("ldmatrix.sync.aligned.m8n8.x4.trans.shared.b16 {%0,%1,%2,%3}, [%4];"
        : "=r"(r[0]), "=r"(r[1]), "=r"(r[2]), "=r"(r[3]) : "r"(addr));
}
__device__ __forceinline__ void mma_f16(float* c, const uint32_t* a, const uint32_t* b) {
    asm volatile(
        "mma.sync.aligned.m16n8k16.row.col.f32.f16.f16.f32 "
        "{%0,%1,%2,%3}, {%4,%5,%6,%7}, {%8,%9}, {%0,%1,%2,%3};"
        : "+f"(c[0]), "+f"(c[1]), "+f"(c[2]), "+f"(c[3])
        : "r"(a[0]), "r"(a[1]), "r"(a[2]), "r"(a[3]), "r"(b[0]), "r"(b[1]));
}
__device__ __forceinline__ void cp16(uint32_t dst, const void* src) {
    asm volatile("cp.async.cg.shared.global [%0], [%1], 16;" :: "r"(dst), "l"(src));
}
__device__ __forceinline__ void cp_commit() { asm volatile("cp.async.commit_group;" ::: "memory"); }
__device__ __forceinline__ void cp_wait1()  { asm volatile("cp.async.wait_group 1;" ::: "memory"); }
__device__ __forceinline__ void cp_wait0()  { asm volatile("cp.async.wait_group 0;" ::: "memory"); }
__device__ __forceinline__ uint32_t pack_h2(__half a, __half b) {
    __half2 v; v.x = a; v.y = b;
    return *reinterpret_cast<uint32_t*>(&v);
}
__device__ __forceinline__ void split1h(float x, __half& h, __half& l) {
    h = __float2half(x);
    l = __float2half(x - __half2float(h));
}

// ======================= pipelined HMMA GEMM (fp16, A split / B rounded) =======================
#define TCBM 128
#define TCBN 128
#define TCBK 32
#define A_PITCH 80
#define B_PITCH 272
#define SM_A_HI 0
#define SM_A_LO 10240
#define SM_B_HI 20480
#define SM_BUF  29184
#define SM_TOT  (2 * SM_BUF)     // 58368

template <bool RELU, bool SPLIT>
__global__ __launch_bounds__(256, 2) void hmma_gemm(
    const __half* __restrict__ Ahi, const __half* __restrict__ Alo,
    const __half* __restrict__ Bhi,
    const float* __restrict__ bias, const float* __restrict__ resid,
    float* __restrict__ C, __half* __restrict__ Chi, __half* __restrict__ Clo,
    int M, int N, int K)
{
    extern __shared__ char smem[];
    const uint32_t sb = smem_u32(smem);

    const int tid = threadIdx.x;
    const int wid = tid >> 5, lane = tid & 31;
    const int warp_m = wid & 1;
    const int warp_n = wid >> 1;
    const int m0 = blockIdx.y * TCBM, n0 = blockIdx.x * TCBN;

    const int aR0 = tid >> 1, aC0 = (tid & 1) << 1;
    const int bR0 = tid >> 3, bC0 = (tid & 7) << 1;

    float c[4][4][4];
    #pragma unroll
    for (int i = 0; i < 4; ++i)
        #pragma unroll
        for (int j = 0; j < 4; ++j)
            #pragma unroll
            for (int f = 0; f < 4; ++f) c[i][j][f] = 0.f;

    const uint32_t a_row = (uint32_t)(warp_m * 64 + (lane & 15));
    const uint32_t a_cb  = (uint32_t)((lane >> 4) << 4);
    const uint32_t b_row = (uint32_t)(lane & 15);
    const uint32_t b_cb  = (uint32_t)(warp_n * 64 + ((lane >> 4) << 4));

    const int NC = K / TCBK;

    auto issue = [&](int ch, int buf) {
        const uint32_t bb = sb + buf * SM_BUF;
        const int k0 = ch * TCBK;
        #pragma unroll
        for (int i = 0; i < 2; ++i) {
            int r = aR0, ck = aC0 + i;
            size_t g = (size_t)(m0 + r) * K + k0 + ck * 8;
            uint32_t d = bb + r * A_PITCH + ck * 16;
            cp16(d + SM_A_HI, Ahi + g);
            cp16(d + SM_A_LO, Alo + g);
        }
        #pragma unroll
        for (int i = 0; i < 2; ++i) {
            int r = bR0, ck = bC0 + i;
            size_t g = (size_t)(k0 + r) * N + n0 + ck * 8;
            cp16(bb + r * B_PITCH + ck * 16 + SM_B_HI, Bhi + g);
        }
        cp_commit();
    };

    issue(0, 0);

    for (int ch = 0; ch < NC; ++ch) {
        const int buf = ch & 1;
        if (ch + 1 < NC) { issue(ch + 1, buf ^ 1); cp_wait1(); }
        else             { cp_wait0(); }
        __syncthreads();

        const uint32_t bb = sb + buf * SM_BUF;
        #pragma unroll
        for (int ks = 0; ks < 2; ++ks) {
            uint32_t bh[4][2];
            uint32_t b_addr = bb + (b_row + ks * 16) * B_PITCH + b_cb;
            #pragma unroll
            for (int nt2 = 0; nt2 < 2; ++nt2) {
                uint32_t t4[4];
                ldm_x4t(t4, b_addr + SM_B_HI + nt2 * 32);
                bh[nt2 * 2][0] = t4[0]; bh[nt2 * 2][1] = t4[1];
                bh[nt2 * 2 + 1][0] = t4[2]; bh[nt2 * 2 + 1][1] = t4[3];
            }
            uint32_t a_addr = bb + a_row * A_PITCH + a_cb + ks * 32;
            #pragma unroll
            for (int mt = 0; mt < 4; ++mt) {
                uint32_t ah[4], al[4];
                ldm_x4(ah, a_addr + SM_A_HI + mt * 16 * A_PITCH);
                ldm_x4(al, a_addr + SM_A_LO + mt * 16 * A_PITCH);
                #pragma unroll
                for (int nt = 0; nt < 4; ++nt) {
                    mma_f16(c[mt][nt], ah, bh[nt]);
                    mma_f16(c[mt][nt], al, bh[nt]);
                }
            }
        }
        __syncthreads();
    }

    const int er = lane >> 2, ec = (lane & 3) * 2;
    #pragma unroll
    for (int mt = 0; mt < 4; ++mt) {
        #pragma unroll
        for (int nt = 0; nt < 4; ++nt) {
            int gr = m0 + warp_m * 64 + mt * 16 + er;
            int gc = n0 + warp_n * 32 + nt * 8 + ec;
            #pragma unroll
            for (int half = 0; half < 2; ++half) {
                int row = gr + half * 8;
                float v0 = c[mt][nt][half * 2 + 0];
                float v1 = c[mt][nt][half * 2 + 1];
                if (bias) { v0 += bias[gc]; v1 += bias[gc + 1]; }
                if (resid) {
                    float2 r2 = *(const float2*)(resid + (size_t)row * N + gc);
                    v0 += r2.x; v1 += r2.y;
                }
                if (RELU) { v0 = fmaxf(v0, 0.f); v1 = fmaxf(v1, 0.f); }
                if (SPLIT) {
                    __half h0, l0, h1, l1;
                    split1h(v0, h0, l0); split1h(v1, h1, l1);
                    *(uint32_t*)(Chi + (size_t)row * N + gc) = pack_h2(h0, h1);
                    *(uint32_t*)(Clo + (size_t)row * N + gc) = pack_h2(l0, l1);
                } else {
                    *(float2*)(C + (size_t)row * N + gc) = make_float2(v0, v1);
                }
            }
        }
    }
}

// ---------------- weight convert: fp32 -> fp16 (hi only) ----------------
__global__ void conv_w(const float* __restrict__ src, __half* __restrict__ hi,
                       int rows, int cols, int dstride, int coff) {
    int idx = blockIdx.x * blockDim.x + threadIdx.x;
    int n4 = rows * cols / 4;
    if (idx >= n4) return;
    float4 v = *(const float4*)(src + idx * 4);
    int e = idx * 4;
    int r = e / cols, cc = e % cols;
    size_t d = (size_t)r * dstride + coff + cc;
    *(uint2*)(hi + d) = make_uint2(pack_h2(__float2half(v.x), __float2half(v.y)),
                                   pack_h2(__float2half(v.z), __float2half(v.w)));
}

// ---------------- block reduction helper ----------------
__device__ __forceinline__ float block_sum_256(float v, float* sred) {
    int lane = threadIdx.x & 31, w = threadIdx.x >> 5;
    #pragma unroll
    for (int o = 16; o; o >>= 1) v += __shfl_xor_sync(0xffffffffu, v, o);
    if (lane == 0) sred[w] = v;
    __syncthreads();
    float r = (threadIdx.x < 8) ? sred[threadIdx.x] : 0.0f;
    if (w == 0) {
        #pragma unroll
        for (int o = 4; o; o >>= 1) r += __shfl_xor_sync(0x000000ffu, r, o);
        if (lane == 0) sred[0] = r;
    }
    __syncthreads();
    float out = sred[0];
    __syncthreads();
    return out;
}

// ---------------- LayerNorm -> fp16 hi/lo ----------------
__global__ void ln_kernel(const float* __restrict__ x, const float* __restrict__ w,
                          const float* __restrict__ b,
                          __half* __restrict__ ohi, __half* __restrict__ olo) {
    __shared__ float sred[8];
    size_t row = blockIdx.x;
    const float* xr = x + row * D_MOD;
    float v[4];
    int t = threadIdx.x;
    #pragma unroll
    for (int j = 0; j < 4; ++j) v[j] = xr[t + 256 * j];
    float s = v[0] + v[1] + v[2] + v[3];
    float mu = block_sum_256(s, sred) * (1.0f / D_MOD);
    float d2 = 0.f;
    #pragma unroll
    for (int j = 0; j < 4; ++j) { float d = v[j] - mu; d2 += d * d; }
    float var = block_sum_256(d2, sred) * (1.0f / D_MOD);
    float inv = rsqrtf(var + LN_EPS);
    #pragma unroll
    for (int j = 0; j < 4; ++j) {
        int idx = t + 256 * j;
        float o = (v[j] - mu) * inv * w[idx] + b[idx];
        __half h, l;
        split1h(o, h, l);
        ohi[row * D_MOD + idx] = h;
        olo[row * D_MOD + idx] = l;
    }
}

// ======================= MMA flash attention (causal, fp16) =======================
// 128 threads, 64 queries, key tiles of 64.
// S = Qhi*Khi + Qhi*Klo + Qlo*Khi (3-term); O += Phi*Vhi + Plo*Vhi (2-term, V rounded).
#define AQ 64
#define APITCH 144
#define ASM_Q_HI 0
#define ASM_Q_LO (64 * APITCH)               //  9216
#define ASM_K_HI (2 * 64 * APITCH)           // 18432
#define ASM_K_LO (3 * 64 * APITCH)           // 27648
#define ASM_V_HI (4 * 64 * APITCH)           // 36864
#define ASM_TOT  (5 * 64 * APITCH)           // 46080

__global__ __launch_bounds__(128) void attn_mma(
    const __half* __restrict__ qkv_hi, const __half* __restrict__ qkv_lo,
    __half* __restrict__ ctx_hi, __half* __restrict__ ctx_lo)
{
    extern __shared__ char sm[];
    const uint32_t sb = smem_u32(sm);
    const int qb = blockIdx.x;
    const int bh = blockIdx.y;
    const int b = bh >> 4, h = bh & 15;
    const int tid = threadIdx.x, w = tid >> 5, lane = tid & 31;
    const size_t tok0 = (size_t)b * S_LEN;
    const int q0 = qb * AQ;
    const int hcol = h * HD;

    // ---- load Q tile (hi/lo) ----
    #pragma unroll
    for (int i = 0; i < 4; ++i) {
        int idx = i * 128 + tid;
        int r = idx >> 3, ck = idx & 7;
        size_t g = (tok0 + q0 + r) * QKV_N + hcol + ck * 8;
        cp16(sb + ASM_Q_HI + r * APITCH + ck * 16, qkv_hi + g);
        cp16(sb + ASM_Q_LO + r * APITCH + ck * 16, qkv_lo + g);
    }
    cp_commit(); cp_wait0();
    __syncthreads();

    uint32_t qh[4][4], ql[4][4];
    {
        uint32_t base = sb + (uint32_t)(w * 16 + (lane & 15)) * APITCH + ((lane >> 4) << 4);
        #pragma unroll
        for (int kt = 0; kt < 4; ++kt) {
            ldm_x4(qh[kt], base + ASM_Q_HI + kt * 32);
            ldm_x4(ql[kt], base + ASM_Q_LO + kt * 32);
        }
    }

    float o[8][4];
    #pragma unroll
    for (int nt = 0; nt < 8; ++nt)
        #pragma unroll
        for (int f = 0; f < 4; ++f) o[nt][f] = 0.f;
    float m0 = -1e30f, m1 = -1e30f, l0 = 0.f, l1 = 0.f;

    const uint32_t krow = (uint32_t)((lane & 7) + ((lane >> 4) << 3));
    const uint32_t kcb  = (uint32_t)(((lane >> 3) & 1) << 4);

    const int ntiles = qb + 1;
    for (int t = 0; t < ntiles; ++t) {
        __syncthreads();
        // ---- load K (hi/lo) + V (hi) ----
        #pragma unroll
        for (int i = 0; i < 4; ++i) {
            int idx = i * 128 + tid;
            int r = idx >> 3, ck = idx & 7;
            size_t gk = (tok0 + t * 64 + r) * QKV_N + hcol + D_MOD + ck * 8;
            uint32_t off = (uint32_t)(r * APITCH + ck * 16);
            cp16(sb + ASM_K_HI + off, qkv_hi + gk);
            cp16(sb + ASM_K_LO + off, qkv_lo + gk);
            cp16(sb + ASM_V_HI + off, qkv_hi + gk + D_MOD);
        }
        cp_commit(); cp_wait0();
        __syncthreads();

        // ---- S = Q K^T (3-term) ----
        float s[8][4];
        #pragma unroll
        for (int nt = 0; nt < 8; ++nt)
            #pragma unroll
            for (int f = 0; f < 4; ++f) s[nt][f] = 0.f;

        #pragma unroll
        for (int kt = 0; kt < 4; ++kt) {
            uint32_t kh[8][2], kl[8][2];
            uint32_t kaddr = sb + krow * APITCH + kcb + kt * 32;
            #pragma unroll
            for (int p = 0; p < 4; ++p) {
                uint32_t t4[4];
                ldm_x4(t4, kaddr + ASM_K_HI + p * 16 * APITCH);
                kh[2 * p][0] = t4[0]; kh[2 * p][1] = t4[1];
                kh[2 * p + 1][0] = t4[2]; kh[2 * p + 1][1] = t4[3];
                ldm_x4(t4, kaddr + ASM_K_LO + p * 16 * APITCH);
                kl[2 * p][0] = t4[0]; kl[2 * p][1] = t4[1];
                kl[2 * p + 1][0] = t4[2]; kl[2 * p + 1][1] = t4[3];
            }
            #pragma unroll
            for (int nt = 0; nt < 8; ++nt) {
                mma_f16(s[nt], qh[kt], kh[nt]);
                mma_f16(s[nt], qh[kt], kl[nt]);
                mma_f16(s[nt], ql[kt], kh[nt]);
            }
        }

        // ---- scale + causal mask ----
        #pragma unroll
        for (int nt = 0; nt < 8; ++nt)
            #pragma unroll
            for (int f = 0; f < 4; ++f) s[nt][f] *= 0.125f;
        if (t == qb) {
            int r0 = w * 16 + (lane >> 2);
            int r1 = r0 + 8;
            #pragma unroll
            for (int nt = 0; nt < 8; ++nt) {
                int c0 = nt * 8 + (lane & 3) * 2;
                if (c0     > r0) s[nt][0] = -1e30f;
                if (c0 + 1 > r0) s[nt][1] = -1e30f;
                if (c0     > r1) s[nt][2] = -1e30f;
                if (c0 + 1 > r1) s[nt][3] = -1e30f;
            }
        }

        // ---- online softmax ----
        float mx0 = -1e30f, mx1 = -1e30f;
        #pragma unroll
        for (int nt = 0; nt < 8; ++nt) {
            mx0 = fmaxf(mx0, fmaxf(s[nt][0], s[nt][1]));
            mx1 = fmaxf(mx1, fmaxf(s[nt][2], s[nt][3]));
        }
        #pragma unroll
        for (int ofs = 1; ofs <= 2; ofs <<= 1) {
            mx0 = fmaxf(mx0, __shfl_xor_sync(0xffffffffu, mx0, ofs));
            mx1 = fmaxf(mx1, __shfl_xor_sync(0xffffffffu, mx1, ofs));
        }
        float mn0 = fmaxf(m0, mx0), mn1 = fmaxf(m1, mx1);
        float cr0 = __expf(m0 - mn0), cr1 = __expf(m1 - mn1);
        float ps0 = 0.f, ps1 = 0.f;
        #pragma unroll
        for (int nt = 0; nt < 8; ++nt) {
            s[nt][0] = __expf(s[nt][0] - mn0);
            s[nt][1] = __expf(s[nt][1] - mn0);
            s[nt][2] = __expf(s[nt][2] - mn1);
            s[nt][3] = __expf(s[nt][3] - mn1);
            ps0 += s[nt][0] + s[nt][1];
            ps1 += s[nt][2] + s[nt][3];
        }
        #pragma unroll
        for (int ofs = 1; ofs <= 2; ofs <<= 1) {
            ps0 += __shfl_xor_sync(0xffffffffu, ps0, ofs);
            ps1 += __shfl_xor_sync(0xffffffffu, ps1, ofs);
        }
        l0 = l0 * cr0 + ps0;
        l1 = l1 * cr1 + ps1;
        m0 = mn0; m1 = mn1;
        #pragma unroll
        for (int nt = 0; nt < 8; ++nt) {
            o[nt][0] *= cr0; o[nt][1] *= cr0;
            o[nt][2] *= cr1; o[nt][3] *= cr1;
        }

        // ---- pack P (split) ----
        uint32_t ph[4][4], pl[4][4];
        #pragma unroll
        for (int t2 = 0; t2 < 4; ++t2) {
            __half hh[8], ll[8];
            #pragma unroll
            for (int j = 0; j < 4; ++j) {
                split1h(s[2 * t2][j], hh[j], ll[j]);
                split1h(s[2 * t2 + 1][j], hh[4 + j], ll[4 + j]);
            }
            ph[t2][0] = pack_h2(hh[0], hh[1]); ph[t2][1] = pack_h2(hh[2], hh[3]);
            ph[t2][2] = pack_h2(hh[4], hh[5]); ph[t2][3] = pack_h2(hh[6], hh[7]);
            pl[t2][0] = pack_h2(ll[0], ll[1]); pl[t2][1] = pack_h2(ll[2], ll[3]);
            pl[t2][2] = pack_h2(ll[4], ll[5]); pl[t2][3] = pack_h2(ll[6], ll[7]);
        }

        // ---- O += P V (2-term) ----
        #pragma unroll
        for (int kt2 = 0; kt2 < 4; ++kt2) {
            uint32_t vh[8][2];
            uint32_t vaddr = sb + (uint32_t)(kt2 * 16 + (lane & 15)) * APITCH + ((lane >> 4) << 4);
            #pragma unroll
            for (int p = 0; p < 4; ++p) {
                uint32_t t4[4];
                ldm_x4t(t4, vaddr + ASM_V_HI + p * 32);
                vh[2 * p][0] = t4[0]; vh[2 * p][1] = t4[1];
                vh[2 * p + 1][0] = t4[2]; vh[2 * p + 1][1] = t4[3];
            }
            #pragma unroll
            for (int nt = 0; nt < 8; ++nt) {
                mma_f16(o[nt], ph[kt2], vh[nt]);
                mma_f16(o[nt], pl[kt2], vh[nt]);
            }
        }
    }

    // ---- write ctx (split) ----
    float i0 = 1.0f / l0, i1 = 1.0f / l1;
    size_t gr0 = tok0 + q0 + w * 16 + (lane >> 2);
    size_t gr1 = gr0 + 8;
    #pragma unroll
    for (int nt = 0; nt < 8; ++nt) {
        int col = hcol + nt * 8 + (lane & 3) * 2;
        float v0 = o[nt][0] * i0, v1 = o[nt][1] * i0;
        float v2 = o[nt][2] * i1, v3 = o[nt][3] * i1;
        __half h0, lo0, h1, lo1, h2, lo2, h3, lo3;
        split1h(v0, h0, lo0); split1h(v1, h1, lo1);
        split1h(v2, h2, lo2); split1h(v3, h3, lo3);
        *(uint32_t*)(ctx_hi + gr0 * D_MOD + col) = pack_h2(h0, h1);
        *(uint32_t*)(ctx_lo + gr0 * D_MOD + col) = pack_h2(lo0, lo1);
        *(uint32_t*)(ctx_hi + gr1 * D_MOD + col) = pack_h2(h2, h3);
        *(uint32_t*)(ctx_lo + gr1 * D_MOD + col) = pack_h2(lo2, lo3);
    }
}

// ---------------- confidence head ----------------
__global__ void pool_kernel(const float* __restrict__ xo, float* __restrict__ pooled) {
    int idx = blockIdx.x * blockDim.x + threadIdx.x;
    int b = idx >> 10, d = idx & 1023;
    const float* p = xo + (size_t)b * S_LEN * D_MOD + d;
    float s = 0.f;
    #pragma unroll 8
    for (int t = 0; t < S_LEN; ++t) s += p[(size_t)t * D_MOD];
    pooled[idx] = s * (1.0f / S_LEN);
}

__global__ void conf_kernel(const float* __restrict__ pooled, const float* __restrict__ cw,
                            const float* __restrict__ cb, float* __restrict__ out) {
    __shared__ float sred[8];
    float acc[B_SZ] = {};
    for (int d = threadIdx.x; d < D_MOD; d += 256) {
        float w = cw[d];
        #pragma unroll
        for (int b = 0; b < B_SZ; ++b) acc[b] += pooled[b * D_MOD + d] * w;
    }
    float dots[B_SZ];
    #pragma unroll
    for (int b = 0; b < B_SZ; ++b) dots[b] = block_sum_256(acc[b], sred);
    if (threadIdx.x == 0) {
        float s = 0.f;
        #pragma unroll
        for (int b = 0; b < B_SZ; ++b) s += 1.0f / (1.0f + __expf(-(dots[b] + cb[0])));
        out[0] = s * (1.0f / B_SZ);
    }
}

// ---------------- host launch ----------------
template <typename T>
static T* sym(const void* s) {
    void* p = nullptr;
    cudaGetSymbolAddress(&p, s);
    return (T*)p;
}

extern "C" void kernel_launch(void* const* d_in, const int* in_sizes, int n_in,
                              void* d_out, int out_size) {
    const float* x      = (const float*)d_in[0];
    const float* Wq     = (const float*)d_in[1];
    const float* Wk     = (const float*)d_in[2];
    const float* Wv     = (const float*)d_in[3];
    const float* Wo     = (const float*)d_in[4];
    const float* ln1_w  = (const float*)d_in[5];
    const float* ln1_b  = (const float*)d_in[6];
    const float* W1     = (const float*)d_in[7];
    const float* b1     = (const float*)d_in[8];
    const float* W2     = (const float*)d_in[9];
    const float* b2     = (const float*)d_in[10];
    const float* ln2_w  = (const float*)d_in[11];
    const float* ln2_b  = (const float*)d_in[12];
    const float* conf_w = (const float*)d_in[13];
    const float* conf_b = (const float*)d_in[14];
    float* out = (float*)d_out;

    __half* h_hi   = sym<__half>(g_h_hi);
    __half* h_lo   = sym<__half>(g_h_lo);
    __half* qkv_hi = sym<__half>(g_qkv_hi);
    __half* qkv_lo = sym<__half>(g_qkv_lo);
    __half* ctx_hi = sym<__half>(g_ctx_hi);
    __half* ctx_lo = sym<__half>(g_ctx_lo);
    float*  x1     = sym<float>(g_x1);
    __half* mid_hi = sym<__half>(g_mid_hi);
    __half* mid_lo = sym<__half>(g_mid_lo);
    float*  pl     = sym<float>(g_pool);
    __half* wqkv_hi = sym<__half>(g_wqkv_hi);
    __half* wo_hi  = sym<__half>(g_wo_hi);
    __half* w1_hi  = sym<__half>(g_w1_hi);
    __half* w2_hi  = sym<__half>(g_w2_hi);

    cudaFuncSetAttribute(hmma_gemm<false, false>, cudaFuncAttributeMaxDynamicSharedMemorySize, SM_TOT);
    cudaFuncSetAttribute(hmma_gemm<false, true >, cudaFuncAttributeMaxDynamicSharedMemorySize, SM_TOT);
    cudaFuncSetAttribute(hmma_gemm<true , true >, cudaFuncAttributeMaxDynamicSharedMemorySize, SM_TOT);
    cudaFuncSetAttribute(attn_mma, cudaFuncAttributeMaxDynamicSharedMemorySize, ASM_TOT);

    // ---- weight conversion (hi only; B-side operands) ----
    {
        int nb = (D_MOD * D_MOD / 4 + 255) / 256;
        conv_w<<<nb, 256>>>(Wq, wqkv_hi, D_MOD, D_MOD, QKV_N, 0);
        conv_w<<<nb, 256>>>(Wk, wqkv_hi, D_MOD, D_MOD, QKV_N, D_MOD);
        conv_w<<<nb, 256>>>(Wv, wqkv_hi, D_MOD, D_MOD, QKV_N, 2 * D_MOD);
        conv_w<<<nb, 256>>>(Wo, wo_hi, D_MOD, D_MOD, D_MOD, 0);
        int nbf = (D_MOD * F_DIM / 4 + 255) / 256;
        conv_w<<<nbf, 256>>>(W1, w1_hi, D_MOD, F_DIM, F_DIM, 0);
        conv_w<<<nbf, 256>>>(W2, w2_hi, F_DIM, D_MOD, D_MOD, 0);
    }

    // LN1 -> split h
    ln_kernel<<<ROWS, 256>>>(x, ln1_w, ln1_b, h_hi, h_lo);
    // fused QKV projection -> split fp16 output
    dim3 gQKV(QKV_N / TCBN, ROWS / TCBM);
    hmma_gemm<false, true><<<gQKV, 256, SM_TOT>>>(h_hi, h_lo, wqkv_hi,
        nullptr, nullptr, nullptr, qkv_hi, qkv_lo, ROWS, QKV_N, D_MOD);
    // causal attention (MMA) -> split ctx
    dim3 gA(S_LEN / AQ, B_SZ * N_HEAD);
    attn_mma<<<gA, 128, ASM_TOT>>>(qkv_hi, qkv_lo, ctx_hi, ctx_lo);
    // out-proj + residual
    dim3 gD(D_MOD / TCBN, ROWS / TCBM);
    hmma_gemm<false, false><<<gD, 256, SM_TOT>>>(ctx_hi, ctx_lo, wo_hi,
        nullptr, x, x1, nullptr, nullptr, ROWS, D_MOD, D_MOD);
    // LN2 -> split h
    ln_kernel<<<ROWS, 256>>>(x1, ln2_w, ln2_b, h_hi, h_lo);
    // FFN1
    dim3 gF(F_DIM / TCBN, ROWS / TCBM);
    hmma_gemm<true, true><<<gF, 256, SM_TOT>>>(h_hi, h_lo, w1_hi,
        b1, nullptr, nullptr, mid_hi, mid_lo, ROWS, F_DIM, D_MOD);
    // FFN2
    hmma_gemm<false, false><<<gD, 256, SM_TOT>>>(mid_hi, mid_lo, w2_hi,
        b2, x1, out, nullptr, nullptr, ROWS, D_MOD, F_DIM);
    // confidence head
    pool_kernel<<<16, 256>>>(out, pl);
    conf_kernel<<<1, 256>>>(pl, conf_w, conf_b, out + (out_size - 1));
}

// round 7
// speedup vs baseline: 5.8217x; 1.6073x over previous
#include <cuda_runtime.h>
#include <cuda_fp16.h>
#include <cstdint>

// Problem constants
#define B_SZ   4
#define S_LEN  2048
#define D_MOD  1024
#define F_DIM  4096
#define N_HEAD 16
#define HD     64
#define ROWS   (B_SZ * S_LEN)        // 8192
#define QKV_N  (3 * D_MOD)           // 3072
#define LN_EPS 1e-5f

// ---------------- scratch (device globals; no allocation) ----------------
__device__ __half g_h  [ROWS * D_MOD];
__device__ __half g_qkv[ROWS * QKV_N];
__device__ __half g_ctx[ROWS * D_MOD];
__device__ float  g_x1 [ROWS * D_MOD];
__device__ __half g_mid[ROWS * F_DIM];
__device__ float  g_pool[B_SZ * D_MOD];
__device__ __half g_wqkv[D_MOD * QKV_N];
__device__ __half g_wo [D_MOD * D_MOD];
__device__ __half g_w1 [D_MOD * F_DIM];
__device__ __half g_w2 [F_DIM * D_MOD];

// ======================= helpers =======================
__device__ __forceinline__ uint32_t smem_u32(const void* p) {
    uint32_t a;
    asm("{ .reg .u64 t; cvta.to.shared.u64 t, %1; cvt.u32.u64 %0, t; }" : "=r"(a) : "l"(p));
    return a;
}
__device__ __forceinline__ void ldm_x4(uint32_t* r, uint32_t addr) {
    asm volatile("ldmatrix.sync.aligned.m8n8.x4.shared.b16 {%0,%1,%2,%3}, [%4];"
        : "=r"(r[0]), "=r"(r[1]), "=r"(r[2]), "=r"(r[3]) : "r"(addr));
}
__device__ __forceinline__ void ldm_x4t(uint32_t* r, uint32_t addr) {
    asm volatile("ldmatrix.sync.aligned.m8n8.x4.trans.shared.b16 {%0,%1,%2,%3}, [%4];"
        : "=r"(r[0]), "=r"(r[1]), "=r"(r[2]), "=r"(r[3]) : "r"(addr));
}
__device__ __forceinline__ void mma_f16(float* c, const uint32_t* a, const uint32_t* b) {
    asm volatile(
        "mma.sync.aligned.m16n8k16.row.col.f32.f16.f16.f32 "
        "{%0,%1,%2,%3}, {%4,%5,%6,%7}, {%8,%9}, {%0,%1,%2,%3};"
        : "+f"(c[0]), "+f"(c[1]), "+f"(c[2]), "+f"(c[3])
        : "r"(a[0]), "r"(a[1]), "r"(a[2]), "r"(a[3]), "r"(b[0]), "r"(b[1]));
}
__device__ __forceinline__ void cp16(uint32_t dst, const void* src) {
    asm volatile("cp.async.cg.shared.global [%0], [%1], 16;" :: "r"(dst), "l"(src));
}
__device__ __forceinline__ void cp_commit() { asm volatile("cp.async.commit_group;" ::: "memory"); }
__device__ __forceinline__ void cp_wait1()  { asm volatile("cp.async.wait_group 1;" ::: "memory"); }
__device__ __forceinline__ void cp_wait0()  { asm volatile("cp.async.wait_group 0;" ::: "memory"); }
__device__ __forceinline__ uint32_t pack_h2(__half a, __half b) {
    __half2 v; v.x = a; v.y = b;
    return *reinterpret_cast<uint32_t*>(&v);
}

// ======================= pipelined HMMA GEMM (fp16, 1-term) =======================
#define TCBM 128
#define TCBN 128
#define TCBK 32
#define A_PITCH 80
#define B_PITCH 272
#define SM_A    0
#define SM_B    10240
#define SM_BUF  18944
#define SM_TOT  (2 * SM_BUF)     // 37888

template <bool RELU, bool SPLIT>
__global__ __launch_bounds__(256, 2) void hmma_gemm(
    const __half* __restrict__ A, const __half* __restrict__ Bm,
    const float* __restrict__ bias, const float* __restrict__ resid,
    float* __restrict__ C, __half* __restrict__ Ch,
    int M, int N, int K)
{
    extern __shared__ char smem[];
    const uint32_t sb = smem_u32(smem);

    const int tid = threadIdx.x;
    const int wid = tid >> 5, lane = tid & 31;
    const int warp_m = wid & 1;
    const int warp_n = wid >> 1;
    const int m0 = blockIdx.y * TCBM, n0 = blockIdx.x * TCBN;

    const int aR0 = tid >> 1, aC0 = (tid & 1) << 1;
    const int bR0 = tid >> 3, bC0 = (tid & 7) << 1;

    float c[4][4][4];
    #pragma unroll
    for (int i = 0; i < 4; ++i)
        #pragma unroll
        for (int j = 0; j < 4; ++j)
            #pragma unroll
            for (int f = 0; f < 4; ++f) c[i][j][f] = 0.f;

    const uint32_t a_row = (uint32_t)(warp_m * 64 + (lane & 15));
    const uint32_t a_cb  = (uint32_t)((lane >> 4) << 4);
    const uint32_t b_row = (uint32_t)(lane & 15);
    const uint32_t b_cb  = (uint32_t)(warp_n * 64 + ((lane >> 4) << 4));

    const int NC = K / TCBK;

    auto issue = [&](int ch, int buf) {
        const uint32_t bb = sb + buf * SM_BUF;
        const int k0 = ch * TCBK;
        #pragma unroll
        for (int i = 0; i < 2; ++i) {
            int ck = aC0 + i;
            size_t g = (size_t)(m0 + aR0) * K + k0 + ck * 8;
            cp16(bb + SM_A + aR0 * A_PITCH + ck * 16, A + g);
        }
        #pragma unroll
        for (int i = 0; i < 2; ++i) {
            int ck = bC0 + i;
            size_t g = (size_t)(k0 + bR0) * N + n0 + ck * 8;
            cp16(bb + SM_B + bR0 * B_PITCH + ck * 16, Bm + g);
        }
        cp_commit();
    };

    issue(0, 0);

    for (int ch = 0; ch < NC; ++ch) {
        const int buf = ch & 1;
        if (ch + 1 < NC) { issue(ch + 1, buf ^ 1); cp_wait1(); }
        else             { cp_wait0(); }
        __syncthreads();

        const uint32_t bb = sb + buf * SM_BUF;
        #pragma unroll
        for (int ks = 0; ks < 2; ++ks) {
            uint32_t bh[4][2];
            uint32_t b_addr = bb + SM_B + (b_row + ks * 16) * B_PITCH + b_cb;
            #pragma unroll
            for (int nt2 = 0; nt2 < 2; ++nt2) {
                uint32_t t4[4];
                ldm_x4t(t4, b_addr + nt2 * 32);
                bh[nt2 * 2][0] = t4[0]; bh[nt2 * 2][1] = t4[1];
                bh[nt2 * 2 + 1][0] = t4[2]; bh[nt2 * 2 + 1][1] = t4[3];
            }
            uint32_t a_addr = bb + SM_A + a_row * A_PITCH + a_cb + ks * 32;
            #pragma unroll
            for (int mt = 0; mt < 4; ++mt) {
                uint32_t ah[4];
                ldm_x4(ah, a_addr + mt * 16 * A_PITCH);
                #pragma unroll
                for (int nt = 0; nt < 4; ++nt)
                    mma_f16(c[mt][nt], ah, bh[nt]);
            }
        }
        __syncthreads();
    }

    const int er = lane >> 2, ec = (lane & 3) * 2;
    #pragma unroll
    for (int mt = 0; mt < 4; ++mt) {
        #pragma unroll
        for (int nt = 0; nt < 4; ++nt) {
            int gr = m0 + warp_m * 64 + mt * 16 + er;
            int gc = n0 + warp_n * 32 + nt * 8 + ec;
            #pragma unroll
            for (int half = 0; half < 2; ++half) {
                int row = gr + half * 8;
                float v0 = c[mt][nt][half * 2 + 0];
                float v1 = c[mt][nt][half * 2 + 1];
                if (bias) { v0 += bias[gc]; v1 += bias[gc + 1]; }
                if (resid) {
                    float2 r2 = *(const float2*)(resid + (size_t)row * N + gc);
                    v0 += r2.x; v1 += r2.y;
                }
                if (RELU) { v0 = fmaxf(v0, 0.f); v1 = fmaxf(v1, 0.f); }
                if (SPLIT) {
                    *(uint32_t*)(Ch + (size_t)row * N + gc) =
                        pack_h2(__float2half(v0), __float2half(v1));
                } else {
                    *(float2*)(C + (size_t)row * N + gc) = make_float2(v0, v1);
                }
            }
        }
    }
}

// ---------------- weight convert: fp32 -> fp16 ----------------
__global__ void conv_w(const float* __restrict__ src, __half* __restrict__ hi,
                       int rows, int cols, int dstride, int coff) {
    int idx = blockIdx.x * blockDim.x + threadIdx.x;
    int n4 = rows * cols / 4;
    if (idx >= n4) return;
    float4 v = *(const float4*)(src + idx * 4);
    int e = idx * 4;
    int r = e / cols, cc = e % cols;
    size_t d = (size_t)r * dstride + coff + cc;
    *(uint2*)(hi + d) = make_uint2(pack_h2(__float2half(v.x), __float2half(v.y)),
                                   pack_h2(__float2half(v.z), __float2half(v.w)));
}

// ---------------- block reduction helper ----------------
__device__ __forceinline__ float block_sum_256(float v, float* sred) {
    int lane = threadIdx.x & 31, w = threadIdx.x >> 5;
    #pragma unroll
    for (int o = 16; o; o >>= 1) v += __shfl_xor_sync(0xffffffffu, v, o);
    if (lane == 0) sred[w] = v;
    __syncthreads();
    float r = (threadIdx.x < 8) ? sred[threadIdx.x] : 0.0f;
    if (w == 0) {
        #pragma unroll
        for (int o = 4; o; o >>= 1) r += __shfl_xor_sync(0x000000ffu, r, o);
        if (lane == 0) sred[0] = r;
    }
    __syncthreads();
    float out = sred[0];
    __syncthreads();
    return out;
}

// ---------------- LayerNorm -> fp16 ----------------
__global__ void ln_kernel(const float* __restrict__ x, const float* __restrict__ w,
                          const float* __restrict__ b, __half* __restrict__ oh) {
    __shared__ float sred[8];
    size_t row = blockIdx.x;
    const float* xr = x + row * D_MOD;
    float v[4];
    int t = threadIdx.x;
    #pragma unroll
    for (int j = 0; j < 4; ++j) v[j] = xr[t + 256 * j];
    float s = v[0] + v[1] + v[2] + v[3];
    float mu = block_sum_256(s, sred) * (1.0f / D_MOD);
    float d2 = 0.f;
    #pragma unroll
    for (int j = 0; j < 4; ++j) { float d = v[j] - mu; d2 += d * d; }
    float var = block_sum_256(d2, sred) * (1.0f / D_MOD);
    float inv = rsqrtf(var + LN_EPS);
    #pragma unroll
    for (int j = 0; j < 4; ++j) {
        int idx = t + 256 * j;
        oh[row * D_MOD + idx] = __float2half((v[j] - mu) * inv * w[idx] + b[idx]);
    }
}

// ======================= MMA flash attention (causal, fp16 1-term) =======================
#define AQ 64
#define APITCH 144
#define ASM_Q 0
#define ASM_K (64 * APITCH)                  //  9216
#define ASM_V (2 * 64 * APITCH)              // 18432
#define ASM_TOT (3 * 64 * APITCH)            // 27648

__global__ __launch_bounds__(128) void attn_mma(
    const __half* __restrict__ qkv, __half* __restrict__ ctx)
{
    extern __shared__ char sm[];
    const uint32_t sb = smem_u32(sm);
    const int qb = blockIdx.x;
    const int bh = blockIdx.y;
    const int b = bh >> 4, h = bh & 15;
    const int tid = threadIdx.x, w = tid >> 5, lane = tid & 31;
    const size_t tok0 = (size_t)b * S_LEN;
    const int q0 = qb * AQ;
    const int hcol = h * HD;

    // ---- load Q tile ----
    #pragma unroll
    for (int i = 0; i < 4; ++i) {
        int idx = i * 128 + tid;
        int r = idx >> 3, ck = idx & 7;
        cp16(sb + ASM_Q + r * APITCH + ck * 16,
             qkv + (tok0 + q0 + r) * QKV_N + hcol + ck * 8);
    }
    cp_commit(); cp_wait0();
    __syncthreads();

    uint32_t qh[4][4];
    {
        uint32_t base = sb + ASM_Q + (uint32_t)(w * 16 + (lane & 15)) * APITCH + ((lane >> 4) << 4);
        #pragma unroll
        for (int kt = 0; kt < 4; ++kt) ldm_x4(qh[kt], base + kt * 32);
    }

    float o[8][4];
    #pragma unroll
    for (int nt = 0; nt < 8; ++nt)
        #pragma unroll
        for (int f = 0; f < 4; ++f) o[nt][f] = 0.f;
    float m0 = -1e30f, m1 = -1e30f, l0 = 0.f, l1 = 0.f;

    const uint32_t krow = (uint32_t)((lane & 7) + ((lane >> 4) << 3));
    const uint32_t kcb  = (uint32_t)(((lane >> 3) & 1) << 4);

    const int ntiles = qb + 1;
    for (int t = 0; t < ntiles; ++t) {
        __syncthreads();
        #pragma unroll
        for (int i = 0; i < 4; ++i) {
            int idx = i * 128 + tid;
            int r = idx >> 3, ck = idx & 7;
            size_t gk = (tok0 + t * 64 + r) * QKV_N + hcol + D_MOD + ck * 8;
            uint32_t off = (uint32_t)(r * APITCH + ck * 16);
            cp16(sb + ASM_K + off, qkv + gk);
            cp16(sb + ASM_V + off, qkv + gk + D_MOD);
        }
        cp_commit(); cp_wait0();
        __syncthreads();

        // ---- S = Q K^T ----
        float s[8][4];
        #pragma unroll
        for (int nt = 0; nt < 8; ++nt)
            #pragma unroll
            for (int f = 0; f < 4; ++f) s[nt][f] = 0.f;

        #pragma unroll
        for (int kt = 0; kt < 4; ++kt) {
            uint32_t kh[8][2];
            uint32_t kaddr = sb + ASM_K + krow * APITCH + kcb + kt * 32;
            #pragma unroll
            for (int p = 0; p < 4; ++p) {
                uint32_t t4[4];
                ldm_x4(t4, kaddr + p * 16 * APITCH);
                kh[2 * p][0] = t4[0]; kh[2 * p][1] = t4[1];
                kh[2 * p + 1][0] = t4[2]; kh[2 * p + 1][1] = t4[3];
            }
            #pragma unroll
            for (int nt = 0; nt < 8; ++nt)
                mma_f16(s[nt], qh[kt], kh[nt]);
        }

        // ---- scale + causal mask ----
        #pragma unroll
        for (int nt = 0; nt < 8; ++nt)
            #pragma unroll
            for (int f = 0; f < 4; ++f) s[nt][f] *= 0.125f;
        if (t == qb) {
            int r0 = w * 16 + (lane >> 2);
            int r1 = r0 + 8;
            #pragma unroll
            for (int nt = 0; nt < 8; ++nt) {
                int c0 = nt * 8 + (lane & 3) * 2;
                if (c0     > r0) s[nt][0] = -1e30f;
                if (c0 + 1 > r0) s[nt][1] = -1e30f;
                if (c0     > r1) s[nt][2] = -1e30f;
                if (c0 + 1 > r1) s[nt][3] = -1e30f;
            }
        }

        // ---- online softmax ----
        float mx0 = -1e30f, mx1 = -1e30f;
        #pragma unroll
        for (int nt = 0; nt < 8; ++nt) {
            mx0 = fmaxf(mx0, fmaxf(s[nt][0], s[nt][1]));
            mx1 = fmaxf(mx1, fmaxf(s[nt][2], s[nt][3]));
        }
        #pragma unroll
        for (int ofs = 1; ofs <= 2; ofs <<= 1) {
            mx0 = fmaxf(mx0, __shfl_xor_sync(0xffffffffu, mx0, ofs));
            mx1 = fmaxf(mx1, __shfl_xor_sync(0xffffffffu, mx1, ofs));
        }
        float mn0 = fmaxf(m0, mx0), mn1 = fmaxf(m1, mx1);
        float cr0 = __expf(m0 - mn0), cr1 = __expf(m1 - mn1);
        float ps0 = 0.f, ps1 = 0.f;
        #pragma unroll
        for (int nt = 0; nt < 8; ++nt) {
            s[nt][0] = __expf(s[nt][0] - mn0);
            s[nt][1] = __expf(s[nt][1] - mn0);
            s[nt][2] = __expf(s[nt][2] - mn1);
            s[nt][3] = __expf(s[nt][3] - mn1);
            ps0 += s[nt][0] + s[nt][1];
            ps1 += s[nt][2] + s[nt][3];
        }
        #pragma unroll
        for (int ofs = 1; ofs <= 2; ofs <<= 1) {
            ps0 += __shfl_xor_sync(0xffffffffu, ps0, ofs);
            ps1 += __shfl_xor_sync(0xffffffffu, ps1, ofs);
        }
        l0 = l0 * cr0 + ps0;
        l1 = l1 * cr1 + ps1;
        m0 = mn0; m1 = mn1;
        #pragma unroll
        for (int nt = 0; nt < 8; ++nt) {
            o[nt][0] *= cr0; o[nt][1] *= cr0;
            o[nt][2] *= cr1; o[nt][3] *= cr1;
        }

        // ---- pack P (rounded) ----
        uint32_t ph[4][4];
        #pragma unroll
        for (int t2 = 0; t2 < 4; ++t2) {
            ph[t2][0] = pack_h2(__float2half(s[2*t2][0]),   __float2half(s[2*t2][1]));
            ph[t2][1] = pack_h2(__float2half(s[2*t2][2]),   __float2half(s[2*t2][3]));
            ph[t2][2] = pack_h2(__float2half(s[2*t2+1][0]), __float2half(s[2*t2+1][1]));
            ph[t2][3] = pack_h2(__float2half(s[2*t2+1][2]), __float2half(s[2*t2+1][3]));
        }

        // ---- O += P V ----
        #pragma unroll
        for (int kt2 = 0; kt2 < 4; ++kt2) {
            uint32_t vh[8][2];
            uint32_t vaddr = sb + ASM_V + (uint32_t)(kt2 * 16 + (lane & 15)) * APITCH + ((lane >> 4) << 4);
            #pragma unroll
            for (int p = 0; p < 4; ++p) {
                uint32_t t4[4];
                ldm_x4t(t4, vaddr + p * 32);
                vh[2 * p][0] = t4[0]; vh[2 * p][1] = t4[1];
                vh[2 * p + 1][0] = t4[2]; vh[2 * p + 1][1] = t4[3];
            }
            #pragma unroll
            for (int nt = 0; nt < 8; ++nt)
                mma_f16(o[nt], ph[kt2], vh[nt]);
        }
    }

    // ---- write ctx ----
    float i0 = 1.0f / l0, i1 = 1.0f / l1;
    size_t gr0 = tok0 + q0 + w * 16 + (lane >> 2);
    size_t gr1 = gr0 + 8;
    #pragma unroll
    for (int nt = 0; nt < 8; ++nt) {
        int col = hcol + nt * 8 + (lane & 3) * 2;
        *(uint32_t*)(ctx + gr0 * D_MOD + col) =
            pack_h2(__float2half(o[nt][0] * i0), __float2half(o[nt][1] * i0));
        *(uint32_t*)(ctx + gr1 * D_MOD + col) =
            pack_h2(__float2half(o[nt][2] * i1), __float2half(o[nt][3] * i1));
    }
}

// ---------------- confidence head ----------------
__global__ void pool_kernel(const float* __restrict__ xo, float* __restrict__ pooled) {
    int idx = blockIdx.x * blockDim.x + threadIdx.x;
    int b = idx >> 10, d = idx & 1023;
    const float* p = xo + (size_t)b * S_LEN * D_MOD + d;
    float s = 0.f;
    #pragma unroll 8
    for (int t = 0; t < S_LEN; ++t) s += p[(size_t)t * D_MOD];
    pooled[idx] = s * (1.0f / S_LEN);
}

__global__ void conf_kernel(const float* __restrict__ pooled, const float* __restrict__ cw,
                            const float* __restrict__ cb, float* __restrict__ out) {
    __shared__ float sred[8];
    float acc[B_SZ] = {};
    for (int d = threadIdx.x; d < D_MOD; d += 256) {
        float w = cw[d];
        #pragma unroll
        for (int b = 0; b < B_SZ; ++b) acc[b] += pooled[b * D_MOD + d] * w;
    }
    float dots[B_SZ];
    #pragma unroll
    for (int b = 0; b < B_SZ; ++b) dots[b] = block_sum_256(acc[b], sred);
    if (threadIdx.x == 0) {
        float s = 0.f;
        #pragma unroll
        for (int b = 0; b < B_SZ; ++b) s += 1.0f / (1.0f + __expf(-(dots[b] + cb[0])));
        out[0] = s * (1.0f / B_SZ);
    }
}

// ---------------- host launch ----------------
template <typename T>
static T* sym(const void* s) {
    void* p = nullptr;
    cudaGetSymbolAddress(&p, s);
    return (T*)p;
}

extern "C" void kernel_launch(void* const* d_in, const int* in_sizes, int n_in,
                              void* d_out, int out_size) {
    const float* x      = (const float*)d_in[0];
    const float* Wq     = (const float*)d_in[1];
    const float* Wk     = (const float*)d_in[2];
    const float* Wv     = (const float*)d_in[3];
    const float* Wo     = (const float*)d_in[4];
    const float* ln1_w  = (const float*)d_in[5];
    const float* ln1_b  = (const float*)d_in[6];
    const float* W1     = (const float*)d_in[7];
    const float* b1     = (const float*)d_in[8];
    const float* W2     = (const float*)d_in[9];
    const float* b2     = (const float*)d_in[10];
    const float* ln2_w  = (const float*)d_in[11];
    const float* ln2_b  = (const float*)d_in[12];
    const float* conf_w = (const float*)d_in[13];
    const float* conf_b = (const float*)d_in[14];
    float* out = (float*)d_out;

    __half* h    = sym<__half>(g_h);
    __half* qkv  = sym<__half>(g_qkv);
    __half* ctx  = sym<__half>(g_ctx);
    float*  x1   = sym<float>(g_x1);
    __half* mid  = sym<__half>(g_mid);
    float*  pl   = sym<float>(g_pool);
    __half* wqkv = sym<__half>(g_wqkv);
    __half* wo   = sym<__half>(g_wo);
    __half* w1   = sym<__half>(g_w1);
    __half* w2   = sym<__half>(g_w2);

    cudaFuncSetAttribute(hmma_gemm<false, false>, cudaFuncAttributeMaxDynamicSharedMemorySize, SM_TOT);
    cudaFuncSetAttribute(hmma_gemm<false, true >, cudaFuncAttributeMaxDynamicSharedMemorySize, SM_TOT);
    cudaFuncSetAttribute(hmma_gemm<true , true >, cudaFuncAttributeMaxDynamicSharedMemorySize, SM_TOT);
    cudaFuncSetAttribute(attn_mma, cudaFuncAttributeMaxDynamicSharedMemorySize, ASM_TOT);

    // ---- weight conversion ----
    {
        int nb = (D_MOD * D_MOD / 4 + 255) / 256;
        conv_w<<<nb, 256>>>(Wq, wqkv, D_MOD, D_MOD, QKV_N, 0);
        conv_w<<<nb, 256>>>(Wk, wqkv, D_MOD, D_MOD, QKV_N, D_MOD);
        conv_w<<<nb, 256>>>(Wv, wqkv, D_MOD, D_MOD, QKV_N, 2 * D_MOD);
        conv_w<<<nb, 256>>>(Wo, wo, D_MOD, D_MOD, D_MOD, 0);
        int nbf = (D_MOD * F_DIM / 4 + 255) / 256;
        conv_w<<<nbf, 256>>>(W1, w1, D_MOD, F_DIM, F_DIM, 0);
        conv_w<<<nbf, 256>>>(W2, w2, F_DIM, D_MOD, D_MOD, 0);
    }

    // LN1 -> fp16 h
    ln_kernel<<<ROWS, 256>>>(x, ln1_w, ln1_b, h);
    // fused QKV projection -> fp16
    dim3 gQKV(QKV_N / TCBN, ROWS / TCBM);
    hmma_gemm<false, true><<<gQKV, 256, SM_TOT>>>(h, wqkv,
        nullptr, nullptr, nullptr, qkv, ROWS, QKV_N, D_MOD);
    // causal attention -> fp16 ctx
    dim3 gA(S_LEN / AQ, B_SZ * N_HEAD);
    attn_mma<<<gA, 128, ASM_TOT>>>(qkv, ctx);
    // out-proj + residual -> fp32 x1
    dim3 gD(D_MOD / TCBN, ROWS / TCBM);
    hmma_gemm<false, false><<<gD, 256, SM_TOT>>>(ctx, wo,
        nullptr, x, x1, nullptr, ROWS, D_MOD, D_MOD);
    // LN2 -> fp16 h
    ln_kernel<<<ROWS, 256>>>(x1, ln2_w, ln2_b, h);
    // FFN1 -> fp16 mid (relu)
    dim3 gF(F_DIM / TCBN, ROWS / TCBM);
    hmma_gemm<true, true><<<gF, 256, SM_TOT>>>(h, w1,
        b1, nullptr, nullptr, mid, ROWS, F_DIM, D_MOD);
    // FFN2 -> out (+b2 + x1)
    hmma_gemm<false, false><<<gD, 256, SM_TOT>>>(mid, w2,
        b2, x1, out, nullptr, ROWS, D_MOD, F_DIM);
    // confidence head
    pool_kernel<<<16, 256>>>(out, pl);
    conf_kernel<<<1, 256>>>(pl, conf_w, conf_b, out + (out_size - 1));
}